// round 13
// baseline (speedup 1.0000x reference)
#include <cuda_runtime.h>
#include <cuda_bf16.h>
#include <cstdint>

#define MAXN   (1<<17)
#define K1     292
#define KT1    19           // layer1 k16-chunks (covers 304; 292..303 zero-pad)
#define LDA1   328          // A1 smem row stride (elems) = 656B (conflict-free ldmatrix)
#define KT2    16
#define LDA2   264          // A2 smem row stride = 528B
#define NH     256
#define MROWS  128
#define NTHR   256

// smem byte offsets
#define SM_A_HI   0
#define SM_A_LO   83968              // 128*328*2
#define SM_B      167936             // 2 buffers x 16384 (hi 8192 + lo 8192)
#define SM_STATC  200704             // 128 rows x 4 ng x float2 = 4096
#define SM_STAT1  204800             // 128 x float2
#define SM_STAT2V 205824
#define SM_STAT2P 206848
#define SMEM_TOTAL 207872

// ===========================================================================
// Device-global weight images / folded params / activation scratch
// ===========================================================================
// B chunk images: per k16-chunk 8192B; elem (n,k): byte = swz(n*32 + (k&15)*2),
// swz: off ^= (n&4)<<2  (conflict-free ldmatrix rows)
__device__ __align__(16) unsigned short g_B1v_hi[KT1*4096], g_B1v_lo[KT1*4096];
__device__ __align__(16) unsigned short g_B1p_hi[KT1*4096], g_B1p_lo[KT1*4096];
__device__ __align__(16) unsigned short g_B2v_hi[KT2*4096], g_B2v_lo[KT2*4096];
__device__ __align__(16) unsigned short g_B2p_hi[KT2*4096], g_B2p_lo[KT2*4096];

__device__ float g_S1v[NH], g_S1p[NH], g_c1v[NH], g_c1p[NH];
__device__ float g_S2v[NH], g_S2p[NH], g_c2v[NH], g_c2p[NH];
__device__ float g_a3v[NH];
__device__ float g_A3p[NH*10];
__device__ float g_S3v, g_c3v;
__device__ float g_S3p[10], g_c3p[10];

__device__ __align__(16) unsigned short g_A2v_hi[(size_t)MAXN*256];
__device__ __align__(16) unsigned short g_A2v_lo[(size_t)MAXN*256];
__device__ __align__(16) unsigned short g_A2p_hi[(size_t)MAXN*256];
__device__ __align__(16) unsigned short g_A2p_lo[(size_t)MAXN*256];

// ===========================================================================
// helpers
// ===========================================================================
__device__ __forceinline__ void split_bf16(float x, unsigned short& hb, unsigned short& lb) {
    __nv_bfloat16 h = __float2bfloat16(x);
    float hf = __bfloat162float(h);
    __nv_bfloat16 l = __float2bfloat16(x - hf);
    hb = *reinterpret_cast<unsigned short*>(&h);
    lb = *reinterpret_cast<unsigned short*>(&l);
}
__device__ __forceinline__ uint32_t smem_u32(const void* p) {
    uint32_t a;
    asm("{ .reg .u64 t; cvta.to.shared.u64 t, %1; cvt.u32.u64 %0, t; }"
        : "=r"(a) : "l"(p));
    return a;
}
__device__ __forceinline__ void cp16(uint32_t dst, const void* src) {
    asm volatile("cp.async.cg.shared.global [%0], [%1], 16;" :: "r"(dst), "l"(src));
}
#define CP_COMMIT() asm volatile("cp.async.commit_group;" ::: "memory")
#define CP_WAIT1()  asm volatile("cp.async.wait_group 1;" ::: "memory")
#define CP_WAIT0()  asm volatile("cp.async.wait_group 0;" ::: "memory")

__device__ __forceinline__ void ldsm_x4(uint32_t addr, uint32_t* r) {
    asm volatile("ldmatrix.sync.aligned.m8n8.x4.shared.b16 {%0,%1,%2,%3}, [%4];"
        : "=r"(r[0]), "=r"(r[1]), "=r"(r[2]), "=r"(r[3]) : "r"(addr));
}
__device__ __forceinline__ void ldsm_x2(uint32_t addr, uint32_t* r) {
    asm volatile("ldmatrix.sync.aligned.m8n8.x2.shared.b16 {%0,%1}, [%2];"
        : "=r"(r[0]), "=r"(r[1]) : "r"(addr));
}
__device__ __forceinline__ void mma_bf16(float* c, const uint32_t* a, const uint32_t* b) {
    asm volatile(
        "mma.sync.aligned.m16n8k16.row.col.f32.bf16.bf16.f32 "
        "{%0,%1,%2,%3}, {%4,%5,%6,%7}, {%8,%9}, {%0,%1,%2,%3};"
        : "+f"(c[0]), "+f"(c[1]), "+f"(c[2]), "+f"(c[3])
        : "r"(a[0]), "r"(a[1]), "r"(a[2]), "r"(a[3]), "r"(b[0]), "r"(b[1]));
}
__device__ __forceinline__ float qsum(float v) {     // sum over lane quad (bits 0,1)
    v += __shfl_xor_sync(0xffffffffu, v, 1);
    v += __shfl_xor_sync(0xffffffffu, v, 2);
    return v;
}

// ===========================================================================
// Prep kernels
// ===========================================================================
__device__ __forceinline__ int bimg_idx(int n, int k) {   // ushort index in chunk image
    int off = n*32 + (k & 15)*2;
    off ^= (n & 4) << 2;
    return ((k >> 4)*8192 + off) >> 1;
}

__global__ void prep1(const float* __restrict__ ln1_w, const float* __restrict__ ln1_b,
                      const float* __restrict__ n1g,  const float* __restrict__ n1b,
                      const float* __restrict__ p1w,  const float* __restrict__ p1b,
                      const float* __restrict__ pn1g, const float* __restrict__ pn1b)
{
    __shared__ float rs[10], rc[10];
    const int tower = blockIdx.x >> 8, n = blockIdx.x & 255, k = threadIdx.x;
    const int wid = k >> 5, lane = k & 31;
    const float* W  = tower ? p1w  : ln1_w;
    const float* bi = tower ? p1b  : ln1_b;
    const float* g  = tower ? pn1g : n1g;
    const float* be = tower ? pn1b : n1b;
    unsigned short* ih = tower ? g_B1p_hi : g_B1v_hi;
    unsigned short* il = tower ? g_B1p_lo : g_B1v_lo;

    float wg = 0.f, wb = 0.f;
    if (k < K1) {
        float w = W[n*K1 + k];
        wg = w * g[k];
        wb = w * be[k];
    }
    if (k < KT1*16) {
        unsigned short hb, lb;
        split_bf16(wg, hb, lb);
        int idx = bimg_idx(n, k);
        ih[idx] = hb;
        il[idx] = lb;
    }
    #pragma unroll
    for (int o = 16; o; o >>= 1) {
        wg += __shfl_xor_sync(0xffffffffu, wg, o);
        wb += __shfl_xor_sync(0xffffffffu, wb, o);
    }
    if (lane == 0) { rs[wid] = wg; rc[wid] = wb; }
    __syncthreads();
    if (k == 0) {
        float S = 0.f, C = 0.f;
        for (int i = 0; i < 10; i++) { S += rs[i]; C += rc[i]; }
        (tower ? g_S1p : g_S1v)[n] = S;
        (tower ? g_c1p : g_c1v)[n] = bi[n] + C;
    }
}

__global__ void prep2(const float* __restrict__ ln2_w, const float* __restrict__ ln2_b,
                      const float* __restrict__ n2g,  const float* __restrict__ n2b,
                      const float* __restrict__ p2w,  const float* __restrict__ p2b,
                      const float* __restrict__ pn2g, const float* __restrict__ pn2b)
{
    __shared__ float rs[8], rc[8];
    const int tower = blockIdx.x >> 8, n = blockIdx.x & 255, k = threadIdx.x;
    const int wid = k >> 5, lane = k & 31;
    const float* W  = tower ? p2w  : ln2_w;
    const float* bi = tower ? p2b  : ln2_b;
    const float* g  = tower ? pn2g : n2g;
    const float* be = tower ? pn2b : n2b;
    unsigned short* ih = tower ? g_B2p_hi : g_B2v_hi;
    unsigned short* il = tower ? g_B2p_lo : g_B2v_lo;

    float w  = W[n*NH + k];
    float wg = w * g[k];
    float wb = w * be[k];
    unsigned short hb, lb;
    split_bf16(wg, hb, lb);
    int idx = bimg_idx(n, k);
    ih[idx] = hb;
    il[idx] = lb;
    #pragma unroll
    for (int o = 16; o; o >>= 1) {
        wg += __shfl_xor_sync(0xffffffffu, wg, o);
        wb += __shfl_xor_sync(0xffffffffu, wb, o);
    }
    if (lane == 0) { rs[wid] = wg; rc[wid] = wb; }
    __syncthreads();
    if (k == 0) {
        float S = 0.f, C = 0.f;
        for (int i = 0; i < 8; i++) { S += rs[i]; C += rc[i]; }
        (tower ? g_S2p : g_S2v)[n] = S;
        (tower ? g_c2p : g_c2v)[n] = bi[n] + C;
    }
}

__global__ void prep3(const float* __restrict__ ln3_w, const float* __restrict__ ln3_b,
                      const float* __restrict__ n3g,  const float* __restrict__ n3b,
                      const float* __restrict__ p3w,  const float* __restrict__ p3b,
                      const float* __restrict__ pn3g, const float* __restrict__ pn3b)
{
    const int n = threadIdx.x;
    g_a3v[n] = ln3_w[n] * n3g[n];
    #pragma unroll
    for (int j = 0; j < 10; j++)
        g_A3p[n*10 + j] = p3w[j*NH + n] * pn3g[n];
    __syncthreads();
    if (n == 0) {
        float S = 0.f, C = 0.f;
        for (int k = 0; k < NH; k++) { S += g_a3v[k]; C += ln3_w[k] * n3b[k]; }
        g_S3v = S; g_c3v = ln3_b[0] + C;
    }
    if (n >= 1 && n <= 10) {
        int j = n - 1;
        float S = 0.f, C = 0.f;
        for (int k = 0; k < NH; k++) { S += g_A3p[k*10 + j]; C += p3w[j*NH + k] * pn3b[k]; }
        g_S3p[j] = S; g_c3p[j] = p3b[j] + C;
    }
}

// ===========================================================================
// Main kernel: raw mma.m16n8k16, warp tile 64 rows x 64 cols
// ===========================================================================
__global__ __launch_bounds__(NTHR, 1)
void bcq_mma(const float* __restrict__ cum, const float* __restrict__ feat,
             const float* __restrict__ pos, float* __restrict__ out, int N)
{
    extern __shared__ char smem[];
    const uint32_t sb = smem_u32(smem);
    const int t = threadIdx.x, wid = t >> 5, l = t & 31;
    const int mg = wid >> 2, ng = wid & 3;          // warp tile: rows mg*64+, cols ng*64+
    const int ql = l >> 2, qc = l & 3;
    const long rowBase = (long)blockIdx.x * MROWS;

    float2* stat1  = (float2*)(smem + SM_STAT1);
    float2* statC  = (float2*)(smem + SM_STATC);
    float2* stat2v = (float2*)(smem + SM_STAT2V);
    float2* stat2p = (float2*)(smem + SM_STAT2P);
    unsigned short* A_hi = (unsigned short*)(smem + SM_A_HI);
    unsigned short* A_lo = (unsigned short*)(smem + SM_A_LO);

    // ---- zero A region (layer1 k-pad 292..303 must be 0) ----
    {
        uint4 z; z.x = z.y = z.z = z.w = 0;
        uint4* a4 = (uint4*)smem;
        for (int i = t; i < 167936/16; i += NTHR) a4[i] = z;
    }
    __syncthreads();

    // ---- phase 1: x -> A1 hi/lo smem + LN1 stats -> stat1 smem ----
    {
        const int row = t >> 1, half = t & 1;
        long gr = rowBase + row;
        long grl = gr < N ? gr : (long)N - 1;
        const float* c0 = cum  + grl * 146;
        const float* f0 = feat + grl * 136;
        const float* p0 = pos  + grl * 10;
        float s = 0.f, ss = 0.f;
        for (int k = half*146; k < half*146 + 146; k++) {
            float x = (k < 146) ? c0[k] : (k < 282 ? f0[k-146] : p0[k-282]);
            s += x; ss += x*x;
            unsigned short hb, lb;
            split_bf16(x, hb, lb);
            A_hi[row*LDA1 + k] = hb;
            A_lo[row*LDA1 + k] = lb;
        }
        s  += __shfl_xor_sync(0xffffffffu, s,  1);
        ss += __shfl_xor_sync(0xffffffffu, ss, 1);
        if (half == 0) {
            const float inv = 1.f / (float)K1;
            float m = s * inv;
            float var = fmaxf(ss * inv - m*m, 0.f);
            stat1[row] = make_float2(m, rsqrtf(var + 1e-5f));
        }
    }
    __syncthreads();

    float c[4][8][4];                 // [mt][nt][c0..c3] accumulators

    // ---- GEMM for one tower-layer ----
    auto gemm = [&](const unsigned short* Bhi, const unsigned short* Blo,
                    int KT, int lda, uint32_t aHi, uint32_t aLo) {
        #pragma unroll
        for (int mt = 0; mt < 4; mt++)
            #pragma unroll
            for (int nt = 0; nt < 8; nt++)
                #pragma unroll
                for (int i = 0; i < 4; i++) c[mt][nt][i] = 0.f;

        auto issue = [&](int ch) {
            uint32_t d0 = sb + SM_B + (ch & 1)*16384;
            const uint4* sh = reinterpret_cast<const uint4*>(Bhi) + ch*512;
            const uint4* sl = reinterpret_cast<const uint4*>(Blo) + ch*512;
            cp16(d0 + t*16,              sh + t);
            cp16(d0 + (t+256)*16,        sh + t + 256);
            cp16(d0 + 8192 + t*16,       sl + t);
            cp16(d0 + 8192 + (t+256)*16, sl + t + 256);
            CP_COMMIT();
        };

        const int arow = l & 15, akh = l >> 4;             // A ldmatrix lane addr
        const int bn  = ng*64 + (l & 7);                   // B base n for this lane
        const int bkh = (l >> 3) & 1;

        issue(0);
        for (int ch = 0; ch < KT; ch++) {
            if (ch + 1 < KT) { issue(ch + 1); CP_WAIT1(); }
            else             { CP_WAIT0(); }
            __syncthreads();
            const uint32_t bbase = sb + SM_B + (ch & 1)*16384;

            uint32_t ah[4][4], al[4][4];
            #pragma unroll
            for (int mt = 0; mt < 4; mt++) {
                uint32_t ao = (uint32_t)(((mg*64 + mt*16 + arow)*lda + ch*16 + akh*8) * 2);
                ldsm_x4(aHi + ao, ah[mt]);
                ldsm_x4(aLo + ao, al[mt]);
            }
            #pragma unroll
            for (int nt = 0; nt < 8; nt++) {
                int n = bn + nt*8;
                uint32_t boff = (uint32_t)(n*32 + bkh*16);
                boff ^= (n & 4) << 2;
                uint32_t bh[2], bl2[2];
                ldsm_x2(bbase + boff, bh);
                ldsm_x2(bbase + 8192 + boff, bl2);
                #pragma unroll
                for (int mt = 0; mt < 4; mt++) {
                    mma_bf16(c[mt][nt], ah[mt], bh);
                    mma_bf16(c[mt][nt], ah[mt], bl2);
                    mma_bf16(c[mt][nt], al[mt], bh);
                }
            }
            __syncthreads();
        }
    };

    // ---- mid epilogue: D -> h(relu) -> global A2 hi/lo; LN2 stats -> stat2 ----
    auto epi_mid = [&](const float* Sg, const float* cvg,
                       unsigned short* gh, unsigned short* gl, float2* stat2) {
        float Sv[16], Cv[16];
        #pragma unroll
        for (int nt = 0; nt < 8; nt++) {
            int n = ng*64 + nt*8 + qc*2;
            Sv[nt*2]   = Sg[n];   Sv[nt*2+1] = Sg[n+1];
            Cv[nt*2]   = cvg[n];  Cv[nt*2+1] = cvg[n+1];
        }
        #pragma unroll
        for (int mt = 0; mt < 4; mt++) {
            const int rl = mg*64 + mt*16 + ql, rh = rl + 8;
            float2 stl = stat1[rl], sth = stat1[rh];
            float sl = 0.f, ssl = 0.f, sh = 0.f, ssh = 0.f;
            #pragma unroll
            for (int nt = 0; nt < 8; nt++) {
                int n = ng*64 + nt*8 + qc*2;
                float* d = c[mt][nt];
                float h00 = fmaxf(stl.y*(d[0] - stl.x*Sv[nt*2])   + Cv[nt*2],   0.f);
                float h01 = fmaxf(stl.y*(d[1] - stl.x*Sv[nt*2+1]) + Cv[nt*2+1], 0.f);
                float h10 = fmaxf(sth.y*(d[2] - sth.x*Sv[nt*2])   + Cv[nt*2],   0.f);
                float h11 = fmaxf(sth.y*(d[3] - sth.x*Sv[nt*2+1]) + Cv[nt*2+1], 0.f);
                sl += h00 + h01; ssl += h00*h00 + h01*h01;
                sh += h10 + h11; ssh += h10*h10 + h11*h11;
                unsigned short h0h, h0l, h1h, h1l, h2h, h2l, h3h, h3l;
                split_bf16(h00, h0h, h0l); split_bf16(h01, h1h, h1l);
                split_bf16(h10, h2h, h2l); split_bf16(h11, h3h, h3l);
                long grl = rowBase + rl, grh = rowBase + rh;
                if (grl < N) {
                    *(uint32_t*)(gh + grl*256 + n) = (uint32_t)h0h | ((uint32_t)h1h << 16);
                    *(uint32_t*)(gl + grl*256 + n) = (uint32_t)h0l | ((uint32_t)h1l << 16);
                }
                if (grh < N) {
                    *(uint32_t*)(gh + grh*256 + n) = (uint32_t)h2h | ((uint32_t)h3h << 16);
                    *(uint32_t*)(gl + grh*256 + n) = (uint32_t)h2l | ((uint32_t)h3l << 16);
                }
            }
            sl = qsum(sl); ssl = qsum(ssl); sh = qsum(sh); ssh = qsum(ssh);
            if (qc == 0) {
                statC[rl*4 + ng] = make_float2(sl, ssl);
                statC[rh*4 + ng] = make_float2(sh, ssh);
            }
        }
        __syncthreads();
        if (ng == 0 && qc == 0) {
            #pragma unroll
            for (int mt = 0; mt < 4; mt++) {
                #pragma unroll
                for (int hh = 0; hh < 2; hh++) {
                    int r = mg*64 + mt*16 + ql + hh*8;
                    float s = 0.f, ss = 0.f;
                    #pragma unroll
                    for (int g = 0; g < 4; g++) {
                        float2 v = statC[r*4 + g];
                        s += v.x; ss += v.y;
                    }
                    const float inv = 1.f / (float)NH;
                    float m = s * inv;
                    float var = fmaxf(ss * inv - m*m, 0.f);
                    stat2[r] = make_float2(m, rsqrtf(var + 1e-5f));
                }
            }
        }
        __syncthreads();
    };

    // ---- copy global A2 -> smem (stride LDA2) ----
    auto copy_A2 = [&](const unsigned short* gh, const unsigned short* gl) {
        for (int i = t; i < 4096; i += NTHR) {
            int row = i >> 5, seg = i & 31;
            long gr = rowBase + row;
            long grl = gr < N ? gr : (long)N - 1;
            uint4 vh = *reinterpret_cast<const uint4*>(gh + grl*256 + seg*8);
            uint4 vl = *reinterpret_cast<const uint4*>(gl + grl*256 + seg*8);
            *reinterpret_cast<uint4*>((char*)A_hi + row*528 + seg*16) = vh;
            *reinterpret_cast<uint4*>((char*)A_lo + row*528 + seg*16) = vl;
        }
        __syncthreads();
    };

    // ======== layer 1 (A1 shared by both towers) ========
    gemm(g_B1v_hi, g_B1v_lo, KT1, LDA1, sb + SM_A_HI, sb + SM_A_LO);
    epi_mid(g_S1v, g_c1v, g_A2v_hi, g_A2v_lo, stat2v);
    gemm(g_B1p_hi, g_B1p_lo, KT1, LDA1, sb + SM_A_HI, sb + SM_A_LO);
    epi_mid(g_S1p, g_c1p, g_A2p_hi, g_A2p_lo, stat2p);

    // ======== layer 2 value + value head ========
    copy_A2(g_A2v_hi, g_A2v_lo);
    gemm(g_B2v_hi, g_B2v_lo, KT2, LDA2, sb + SM_A_HI, sb + SM_A_LO);
    {
        float Sv[16], Cv[16], A3[16];
        #pragma unroll
        for (int nt = 0; nt < 8; nt++) {
            int n = ng*64 + nt*8 + qc*2;
            Sv[nt*2] = g_S2v[n]; Sv[nt*2+1] = g_S2v[n+1];
            Cv[nt*2] = g_c2v[n]; Cv[nt*2+1] = g_c2v[n+1];
            A3[nt*2] = g_a3v[n]; A3[nt*2+1] = g_a3v[n+1];
        }
        float4* vstat = (float4*)(smem + SM_B);
        #pragma unroll
        for (int mt = 0; mt < 4; mt++) {
            const int rl = mg*64 + mt*16 + ql, rh = rl + 8;
            float2 stl = stat2v[rl], sth = stat2v[rh];
            float sl = 0.f, ssl = 0.f, vdl = 0.f, sh = 0.f, ssh = 0.f, vdh = 0.f;
            #pragma unroll
            for (int nt = 0; nt < 8; nt++) {
                float* d = c[mt][nt];
                float h00 = fmaxf(stl.y*(d[0] - stl.x*Sv[nt*2])   + Cv[nt*2],   0.f);
                float h01 = fmaxf(stl.y*(d[1] - stl.x*Sv[nt*2+1]) + Cv[nt*2+1], 0.f);
                float h10 = fmaxf(sth.y*(d[2] - sth.x*Sv[nt*2])   + Cv[nt*2],   0.f);
                float h11 = fmaxf(sth.y*(d[3] - sth.x*Sv[nt*2+1]) + Cv[nt*2+1], 0.f);
                sl += h00 + h01; ssl += h00*h00 + h01*h01;
                sh += h10 + h11; ssh += h10*h10 + h11*h11;
                vdl = fmaf(A3[nt*2], h00, fmaf(A3[nt*2+1], h01, vdl));
                vdh = fmaf(A3[nt*2], h10, fmaf(A3[nt*2+1], h11, vdh));
            }
            sl = qsum(sl); ssl = qsum(ssl); vdl = qsum(vdl);
            sh = qsum(sh); ssh = qsum(ssh); vdh = qsum(vdh);
            if (qc == 0) {
                vstat[rl*4 + ng] = make_float4(sl, ssl, vdl, 0.f);
                vstat[rh*4 + ng] = make_float4(sh, ssh, vdh, 0.f);
            }
        }
        __syncthreads();
        if (ng == 0 && qc == 0) {
            #pragma unroll
            for (int mt = 0; mt < 4; mt++) {
                #pragma unroll
                for (int hh = 0; hh < 2; hh++) {
                    int r = mg*64 + mt*16 + ql + hh*8;
                    float s = 0.f, ss = 0.f, vd = 0.f;
                    #pragma unroll
                    for (int g = 0; g < 4; g++) {
                        float4 v = vstat[r*4 + g];
                        s += v.x; ss += v.y; vd += v.z;
                    }
                    long gr = rowBase + r;
                    if (gr < N) {
                        const float inv = 1.f / (float)NH;
                        float m3 = s * inv;
                        float var3 = fmaxf(ss * inv - m3*m3, 0.f);
                        float rs3 = rsqrtf(var3 + 1e-5f);
                        out[gr] = rs3*(vd - m3*g_S3v) + g_c3v;
                    }
                }
            }
        }
        __syncthreads();
    }

    // ======== layer 2 prob + prob head (log_softmax) ========
    copy_A2(g_A2p_hi, g_A2p_lo);
    gemm(g_B2p_hi, g_B2p_lo, KT2, LDA2, sb + SM_A_HI, sb + SM_A_LO);
    {
        float Sv[16], Cv[16];
        #pragma unroll
        for (int nt = 0; nt < 8; nt++) {
            int n = ng*64 + nt*8 + qc*2;
            Sv[nt*2] = g_S2p[n]; Sv[nt*2+1] = g_S2p[n+1];
            Cv[nt*2] = g_c2p[n]; Cv[nt*2+1] = g_c2p[n+1];
        }
        float* pstat = (float*)(smem + SM_B);   // [128][4][12]
        #pragma unroll
        for (int mt = 0; mt < 4; mt++) {
            const int rl = mg*64 + mt*16 + ql, rh = rl + 8;
            float2 stl = stat2p[rl], sth = stat2p[rh];
            float sl = 0.f, ssl = 0.f, sh = 0.f, ssh = 0.f;
            float Pl[10], Ph[10];
            #pragma unroll
            for (int q = 0; q < 10; q++) { Pl[q] = 0.f; Ph[q] = 0.f; }
            #pragma unroll
            for (int nt = 0; nt < 8; nt++) {
                int n = ng*64 + nt*8 + qc*2;
                float* d = c[mt][nt];
                float h00 = fmaxf(stl.y*(d[0] - stl.x*Sv[nt*2])   + Cv[nt*2],   0.f);
                float h01 = fmaxf(stl.y*(d[1] - stl.x*Sv[nt*2+1]) + Cv[nt*2+1], 0.f);
                float h10 = fmaxf(sth.y*(d[2] - sth.x*Sv[nt*2])   + Cv[nt*2],   0.f);
                float h11 = fmaxf(sth.y*(d[3] - sth.x*Sv[nt*2+1]) + Cv[nt*2+1], 0.f);
                sl += h00 + h01; ssl += h00*h00 + h01*h01;
                sh += h10 + h11; ssh += h10*h10 + h11*h11;
                const float* a0 = g_A3p + n*10;
                const float* a1 = a0 + 10;
                #pragma unroll
                for (int q = 0; q < 10; q++) {
                    Pl[q] = fmaf(h00, a0[q], fmaf(h01, a1[q], Pl[q]));
                    Ph[q] = fmaf(h10, a0[q], fmaf(h11, a1[q], Ph[q]));
                }
            }
            sl = qsum(sl); ssl = qsum(ssl); sh = qsum(sh); ssh = qsum(ssh);
            #pragma unroll
            for (int q = 0; q < 10; q++) { Pl[q] = qsum(Pl[q]); Ph[q] = qsum(Ph[q]); }
            if (qc == 0) {
                float* pl = pstat + (rl*4 + ng)*12;
                float* ph = pstat + (rh*4 + ng)*12;
                pl[0] = sl; pl[1] = ssl;
                ph[0] = sh; ph[1] = ssh;
                #pragma unroll
                for (int q = 0; q < 10; q++) { pl[2+q] = Pl[q]; ph[2+q] = Ph[q]; }
            }
        }
        __syncthreads();
        if (ng == 0 && qc == 0) {
            #pragma unroll
            for (int mt = 0; mt < 4; mt++) {
                #pragma unroll
                for (int hh = 0; hh < 2; hh++) {
                    int r = mg*64 + mt*16 + ql + hh*8;
                    float s = 0.f, ss = 0.f;
                    float P[10];
                    #pragma unroll
                    for (int q = 0; q < 10; q++) P[q] = 0.f;
                    #pragma unroll
                    for (int g = 0; g < 4; g++) {
                        const float* v = pstat + (r*4 + g)*12;
                        s += v[0]; ss += v[1];
                        #pragma unroll
                        for (int q = 0; q < 10; q++) P[q] += v[2+q];
                    }
                    long gr = rowBase + r;
                    if (gr < N) {
                        const float inv = 1.f / (float)NH;
                        float m3 = s * inv;
                        float var3 = fmaxf(ss * inv - m3*m3, 0.f);
                        float rs3 = rsqrtf(var3 + 1e-5f);
                        float sc[10];
                        float mx = -3.4e38f;
                        #pragma unroll
                        for (int q = 0; q < 10; q++) {
                            sc[q] = rs3*(P[q] - m3*g_S3p[q]) + g_c3p[q];
                            mx = fmaxf(mx, sc[q]);
                        }
                        float se = 0.f;
                        #pragma unroll
                        for (int q = 0; q < 10; q++) se += expf(sc[q] - mx);
                        float lse = mx + logf(se);
                        float* lp = out + N + gr * 10;
                        float* so = out + N + (long)N * 10 + gr * 10;
                        #pragma unroll
                        for (int q = 0; q < 10; q++) {
                            lp[q] = sc[q] - lse;
                            so[q] = sc[q];
                        }
                    }
                }
            }
        }
    }
}

// ===========================================================================
extern "C" void kernel_launch(void* const* d_in, const int* in_sizes, int n_in,
                              void* d_out, int out_size) {
    const float* cum  = (const float*)d_in[0];
    const float* feat = (const float*)d_in[1];
    const float* pos  = (const float*)d_in[2];
    const int N = in_sizes[0] / 146;

    cudaFuncSetAttribute(bcq_mma, cudaFuncAttributeMaxDynamicSharedMemorySize, SMEM_TOTAL);

    prep1<<<512, 320>>>(
        (const float*)d_in[3],  (const float*)d_in[4],    // ln1_w, ln1_b
        (const float*)d_in[9],  (const float*)d_in[10],   // norm1_g, norm1_b
        (const float*)d_in[15], (const float*)d_in[16],   // prob1_w, prob1_b
        (const float*)d_in[21], (const float*)d_in[22]);  // pnorm1_g, pnorm1_b
    prep2<<<512, 256>>>(
        (const float*)d_in[5],  (const float*)d_in[6],    // ln2_w, ln2_b
        (const float*)d_in[11], (const float*)d_in[12],   // norm2_g, norm2_b
        (const float*)d_in[17], (const float*)d_in[18],   // prob2_w, prob2_b
        (const float*)d_in[23], (const float*)d_in[24]);  // pnorm2_g, pnorm2_b
    prep3<<<1, 256>>>(
        (const float*)d_in[7],  (const float*)d_in[8],    // ln3_w, ln3_b
        (const float*)d_in[13], (const float*)d_in[14],   // norm3_g, norm3_b
        (const float*)d_in[19], (const float*)d_in[20],   // prob3_w, prob3_b
        (const float*)d_in[25], (const float*)d_in[26]);  // pnorm3_g, pnorm3_b

    const int grid = (N + MROWS - 1) / MROWS;
    bcq_mma<<<grid, NTHR, SMEM_TOTAL>>>(cum, feat, pos, (float*)d_out, N);
}

// round 14
// speedup vs baseline: 1.7609x; 1.7609x over previous
#include <cuda_runtime.h>
#include <cuda_bf16.h>
#include <cstdint>

#define MAXN   (1<<17)
#define K1     292
#define KT1    19           // layer1 k16-chunks (covers 304; 292..303 zero-pad)
#define LDA1   328          // A1 smem row stride (elems) = 656B (conflict-free ldmatrix)
#define KT2    16
#define LDA2   264          // A2 smem row stride = 528B
#define NH     256
#define MROWS  64
#define NTHR   256

// smem byte offsets (total 95.5KB -> 2 CTAs/SM)
#define SM_A_HI    0                 // 64*328*2 = 41984
#define SM_A_LO    41984
#define SM_SCRATCH 83968             // 12288: statC / vstat / pstat (time-shared)
#define SM_STAT1   96256             // 64 x float2
#define SM_STAT2V  96768
#define SM_STAT2P  97280
#define SMEM_TOTAL 97792

// ===========================================================================
// Weight images in mma-fragment order:
// uint4 idx = (ch*32 + n/8)*32 + lane,  lane = (n&7)*4 + ((k&7)>>1)
//   .x = hi b0 (k%16 in 0..7), .y = hi b1 (8..15), .z = lo b0, .w = lo b1
//   16-bit half within word = k&1
// ===========================================================================
__device__ __align__(16) uint4 g_B1v[KT1*1024], g_B1p[KT1*1024];
__device__ __align__(16) uint4 g_B2v[KT2*1024], g_B2p[KT2*1024];

__device__ float g_S1v[NH], g_S1p[NH], g_c1v[NH], g_c1p[NH];
__device__ float g_S2v[NH], g_S2p[NH], g_c2v[NH], g_c2p[NH];
__device__ float g_a3v[NH];
__device__ float g_A3p[NH*10];
__device__ float g_S3v, g_c3v;
__device__ float g_S3p[10], g_c3p[10];

__device__ __align__(16) unsigned short g_A2v_hi[(size_t)MAXN*256];
__device__ __align__(16) unsigned short g_A2v_lo[(size_t)MAXN*256];
__device__ __align__(16) unsigned short g_A2p_hi[(size_t)MAXN*256];
__device__ __align__(16) unsigned short g_A2p_lo[(size_t)MAXN*256];

// ===========================================================================
// helpers
// ===========================================================================
__device__ __forceinline__ void split_bf16(float x, unsigned short& hb, unsigned short& lb) {
    __nv_bfloat16 h = __float2bfloat16(x);
    float hf = __bfloat162float(h);
    __nv_bfloat16 l = __float2bfloat16(x - hf);
    hb = *reinterpret_cast<unsigned short*>(&h);
    lb = *reinterpret_cast<unsigned short*>(&l);
}
__device__ __forceinline__ uint32_t smem_u32(const void* p) {
    uint32_t a;
    asm("{ .reg .u64 t; cvta.to.shared.u64 t, %1; cvt.u32.u64 %0, t; }"
        : "=r"(a) : "l"(p));
    return a;
}
__device__ __forceinline__ void ldsm_x4(uint32_t addr, uint32_t* r) {
    asm volatile("ldmatrix.sync.aligned.m8n8.x4.shared.b16 {%0,%1,%2,%3}, [%4];"
        : "=r"(r[0]), "=r"(r[1]), "=r"(r[2]), "=r"(r[3]) : "r"(addr));
}
__device__ __forceinline__ void mma_bf16(float* c, const uint32_t* a, uint32_t b0, uint32_t b1) {
    asm volatile(
        "mma.sync.aligned.m16n8k16.row.col.f32.bf16.bf16.f32 "
        "{%0,%1,%2,%3}, {%4,%5,%6,%7}, {%8,%9}, {%0,%1,%2,%3};"
        : "+f"(c[0]), "+f"(c[1]), "+f"(c[2]), "+f"(c[3])
        : "r"(a[0]), "r"(a[1]), "r"(a[2]), "r"(a[3]), "r"(b0), "r"(b1));
}
__device__ __forceinline__ float qsum(float v) {
    v += __shfl_xor_sync(0xffffffffu, v, 1);
    v += __shfl_xor_sync(0xffffffffu, v, 2);
    return v;
}

// fragment-order ushort index (hi part; lo = +4)
__device__ __forceinline__ size_t bimg_us(int n, int k) {
    int ch = k >> 4, kk = k & 15;
    int j = n >> 3, gid = n & 7, tig = (kk & 7) >> 1, kin = kk & 1, kh = kk >> 3;
    return ((((size_t)ch*32 + j)*32 + gid*4 + tig) * 8) + kh*2 + kin;
}

// ===========================================================================
// Prep kernels
// ===========================================================================
__global__ void prep1(const float* __restrict__ ln1_w, const float* __restrict__ ln1_b,
                      const float* __restrict__ n1g,  const float* __restrict__ n1b,
                      const float* __restrict__ p1w,  const float* __restrict__ p1b,
                      const float* __restrict__ pn1g, const float* __restrict__ pn1b)
{
    __shared__ float rs[10], rc[10];
    const int tower = blockIdx.x >> 8, n = blockIdx.x & 255, k = threadIdx.x;
    const int wid = k >> 5, lane = k & 31;
    const float* W  = tower ? p1w  : ln1_w;
    const float* bi = tower ? p1b  : ln1_b;
    const float* g  = tower ? pn1g : n1g;
    const float* be = tower ? pn1b : n1b;
    unsigned short* img = (unsigned short*)(tower ? g_B1p : g_B1v);

    float wg = 0.f, wb = 0.f;
    if (k < K1) {
        float w = W[n*K1 + k];
        wg = w * g[k];
        wb = w * be[k];
    }
    if (k < KT1*16) {
        unsigned short hb, lb;
        split_bf16(wg, hb, lb);
        size_t idx = bimg_us(n, k);
        img[idx]     = hb;
        img[idx + 4] = lb;
    }
    #pragma unroll
    for (int o = 16; o; o >>= 1) {
        wg += __shfl_xor_sync(0xffffffffu, wg, o);
        wb += __shfl_xor_sync(0xffffffffu, wb, o);
    }
    if (lane == 0) { rs[wid] = wg; rc[wid] = wb; }
    __syncthreads();
    if (k == 0) {
        float S = 0.f, C = 0.f;
        for (int i = 0; i < 10; i++) { S += rs[i]; C += rc[i]; }
        (tower ? g_S1p : g_S1v)[n] = S;
        (tower ? g_c1p : g_c1v)[n] = bi[n] + C;
    }
}

__global__ void prep2(const float* __restrict__ ln2_w, const float* __restrict__ ln2_b,
                      const float* __restrict__ n2g,  const float* __restrict__ n2b,
                      const float* __restrict__ p2w,  const float* __restrict__ p2b,
                      const float* __restrict__ pn2g, const float* __restrict__ pn2b)
{
    __shared__ float rs[8], rc[8];
    const int tower = blockIdx.x >> 8, n = blockIdx.x & 255, k = threadIdx.x;
    const int wid = k >> 5, lane = k & 31;
    const float* W  = tower ? p2w  : ln2_w;
    const float* bi = tower ? p2b  : ln2_b;
    const float* g  = tower ? pn2g : n2g;
    const float* be = tower ? pn2b : n2b;
    unsigned short* img = (unsigned short*)(tower ? g_B2p : g_B2v);

    float w  = W[n*NH + k];
    float wg = w * g[k];
    float wb = w * be[k];
    unsigned short hb, lb;
    split_bf16(wg, hb, lb);
    size_t idx = bimg_us(n, k);
    img[idx]     = hb;
    img[idx + 4] = lb;
    #pragma unroll
    for (int o = 16; o; o >>= 1) {
        wg += __shfl_xor_sync(0xffffffffu, wg, o);
        wb += __shfl_xor_sync(0xffffffffu, wb, o);
    }
    if (lane == 0) { rs[wid] = wg; rc[wid] = wb; }
    __syncthreads();
    if (k == 0) {
        float S = 0.f, C = 0.f;
        for (int i = 0; i < 8; i++) { S += rs[i]; C += rc[i]; }
        (tower ? g_S2p : g_S2v)[n] = S;
        (tower ? g_c2p : g_c2v)[n] = bi[n] + C;
    }
}

__global__ void prep3(const float* __restrict__ ln3_w, const float* __restrict__ ln3_b,
                      const float* __restrict__ n3g,  const float* __restrict__ n3b,
                      const float* __restrict__ p3w,  const float* __restrict__ p3b,
                      const float* __restrict__ pn3g, const float* __restrict__ pn3b)
{
    const int n = threadIdx.x;
    g_a3v[n] = ln3_w[n] * n3g[n];
    #pragma unroll
    for (int j = 0; j < 10; j++)
        g_A3p[n*10 + j] = p3w[j*NH + n] * pn3g[n];
    __syncthreads();
    if (n == 0) {
        float S = 0.f, C = 0.f;
        for (int k = 0; k < NH; k++) { S += g_a3v[k]; C += ln3_w[k] * n3b[k]; }
        g_S3v = S; g_c3v = ln3_b[0] + C;
    }
    if (n >= 1 && n <= 10) {
        int j = n - 1;
        float S = 0.f, C = 0.f;
        for (int k = 0; k < NH; k++) { S += g_A3p[k*10 + j]; C += p3w[j*NH + k] * pn3b[k]; }
        g_S3p[j] = S; g_c3p[j] = p3b[j] + C;
    }
}

// ===========================================================================
// Main kernel: 64 rows/CTA, warp tile 32x64, B from L2 in fragment order
// ===========================================================================
__global__ __launch_bounds__(NTHR, 2)
void bcq_mma(const float* __restrict__ cum, const float* __restrict__ feat,
             const float* __restrict__ pos, float* __restrict__ out, int N)
{
    extern __shared__ char smem[];
    const uint32_t sb = smem_u32(smem);
    const int t = threadIdx.x, wid = t >> 5, l = t & 31;
    const int mg = wid >> 2, ng = wid & 3;          // rows mg*32+, cols ng*64+
    const int ql = l >> 2, qc = l & 3;
    const long rowBase = (long)blockIdx.x * MROWS;

    float2* stat1  = (float2*)(smem + SM_STAT1);
    float2* statC  = (float2*)(smem + SM_SCRATCH);
    float2* stat2v = (float2*)(smem + SM_STAT2V);
    float2* stat2p = (float2*)(smem + SM_STAT2P);
    unsigned short* A_hi = (unsigned short*)(smem + SM_A_HI);
    unsigned short* A_lo = (unsigned short*)(smem + SM_A_LO);

    // ---- zero A region (layer1 k-pad 292..303 must be 0) ----
    {
        uint4 z; z.x = z.y = z.z = z.w = 0;
        uint4* a4 = (uint4*)smem;
        for (int i = t; i < 83968/16; i += NTHR) a4[i] = z;
    }
    __syncthreads();

    // ---- phase 1: x -> A1 hi/lo smem + LN1 stats ----
    {
        const int row = t >> 2, q = t & 3;          // 64 rows x 4 quarters
        long gr = rowBase + row;
        long grl = gr < N ? gr : (long)N - 1;
        const float* c0 = cum  + grl * 146;
        const float* f0 = feat + grl * 136;
        const float* p0 = pos  + grl * 10;
        float s = 0.f, ss = 0.f;
        for (int k = q*73; k < q*73 + 73; k++) {
            float x = (k < 146) ? c0[k] : (k < 282 ? f0[k-146] : p0[k-282]);
            s += x; ss += x*x;
            unsigned short hb, lb;
            split_bf16(x, hb, lb);
            A_hi[row*LDA1 + k] = hb;
            A_lo[row*LDA1 + k] = lb;
        }
        s = qsum(s); ss = qsum(ss);
        if (q == 0) {
            const float inv = 1.f / (float)K1;
            float m = s * inv;
            float var = fmaxf(ss * inv - m*m, 0.f);
            stat1[row] = make_float2(m, rsqrtf(var + 1e-5f));
        }
    }
    __syncthreads();

    float c[2][8][4];                 // [mt][nt][4]

    // ---- GEMM: no smem-B, no barriers; B LDG.128 from L2 (fragment order) ----
    auto gemm = [&](const uint4* __restrict__ Bimg, int KT, int lda, uint32_t aHi, uint32_t aLo) {
        #pragma unroll
        for (int mt = 0; mt < 2; mt++)
            #pragma unroll
            for (int nt = 0; nt < 8; nt++)
                #pragma unroll
                for (int i = 0; i < 4; i++) c[mt][nt][i] = 0.f;

        const int arow = l & 15, akh = l >> 4;
        const uint4* Bp = Bimg + (ng*8)*32 + l;

        #pragma unroll 1
        for (int ch = 0; ch < KT; ch++) {
            uint32_t ah[2][4], al[2][4];
            #pragma unroll
            for (int mt = 0; mt < 2; mt++) {
                uint32_t ao = (uint32_t)(((mg*32 + mt*16 + arow)*lda + ch*16 + akh*8) * 2);
                ldsm_x4(aHi + ao, ah[mt]);
                ldsm_x4(aLo + ao, al[mt]);
            }
            uint4 bv[8];
            #pragma unroll
            for (int nt = 0; nt < 8; nt++) bv[nt] = Bp[ch*1024 + nt*32];
            #pragma unroll
            for (int nt = 0; nt < 8; nt++) {
                #pragma unroll
                for (int mt = 0; mt < 2; mt++) {
                    mma_bf16(c[mt][nt], ah[mt], bv[nt].x, bv[nt].y);
                    mma_bf16(c[mt][nt], ah[mt], bv[nt].z, bv[nt].w);
                    mma_bf16(c[mt][nt], al[mt], bv[nt].x, bv[nt].y);
                }
            }
        }
    };

    // ---- mid epilogue: D -> h(relu) -> global A2 hi/lo; LN2 stats -> stat2 ----
    auto epi_mid = [&](const float* Sg, const float* cvg,
                       unsigned short* gh, unsigned short* gl, float2* stat2) {
        float Sv[16], Cv[16];
        #pragma unroll
        for (int nt = 0; nt < 8; nt++) {
            int n = ng*64 + nt*8 + qc*2;
            Sv[nt*2]   = Sg[n];   Sv[nt*2+1] = Sg[n+1];
            Cv[nt*2]   = cvg[n];  Cv[nt*2+1] = cvg[n+1];
        }
        #pragma unroll
        for (int mt = 0; mt < 2; mt++) {
            const int rl = mg*32 + mt*16 + ql, rh = rl + 8;
            float2 stl = stat1[rl], sth = stat1[rh];
            float sl = 0.f, ssl = 0.f, sh = 0.f, ssh = 0.f;
            #pragma unroll
            for (int nt = 0; nt < 8; nt++) {
                int n = ng*64 + nt*8 + qc*2;
                float* d = c[mt][nt];
                float h00 = fmaxf(stl.y*(d[0] - stl.x*Sv[nt*2])   + Cv[nt*2],   0.f);
                float h01 = fmaxf(stl.y*(d[1] - stl.x*Sv[nt*2+1]) + Cv[nt*2+1], 0.f);
                float h10 = fmaxf(sth.y*(d[2] - sth.x*Sv[nt*2])   + Cv[nt*2],   0.f);
                float h11 = fmaxf(sth.y*(d[3] - sth.x*Sv[nt*2+1]) + Cv[nt*2+1], 0.f);
                sl += h00 + h01; ssl += h00*h00 + h01*h01;
                sh += h10 + h11; ssh += h10*h10 + h11*h11;
                unsigned short h0h, h0l, h1h, h1l, h2h, h2l, h3h, h3l;
                split_bf16(h00, h0h, h0l); split_bf16(h01, h1h, h1l);
                split_bf16(h10, h2h, h2l); split_bf16(h11, h3h, h3l);
                long grl = rowBase + rl, grh = rowBase + rh;
                if (grl < N) {
                    *(uint32_t*)(gh + grl*256 + n) = (uint32_t)h0h | ((uint32_t)h1h << 16);
                    *(uint32_t*)(gl + grl*256 + n) = (uint32_t)h0l | ((uint32_t)h1l << 16);
                }
                if (grh < N) {
                    *(uint32_t*)(gh + grh*256 + n) = (uint32_t)h2h | ((uint32_t)h3h << 16);
                    *(uint32_t*)(gl + grh*256 + n) = (uint32_t)h2l | ((uint32_t)h3l << 16);
                }
            }
            sl = qsum(sl); ssl = qsum(ssl); sh = qsum(sh); ssh = qsum(ssh);
            if (qc == 0) {
                statC[rl*4 + ng] = make_float2(sl, ssl);
                statC[rh*4 + ng] = make_float2(sh, ssh);
            }
        }
        __syncthreads();
        if (ng == 0 && qc == 0) {
            #pragma unroll
            for (int mt = 0; mt < 2; mt++) {
                #pragma unroll
                for (int hh = 0; hh < 2; hh++) {
                    int r = mg*32 + mt*16 + ql + hh*8;
                    float s = 0.f, ss = 0.f;
                    #pragma unroll
                    for (int g = 0; g < 4; g++) {
                        float2 v = statC[r*4 + g];
                        s += v.x; ss += v.y;
                    }
                    const float inv = 1.f / (float)NH;
                    float m = s * inv;
                    float var = fmaxf(ss * inv - m*m, 0.f);
                    stat2[r] = make_float2(m, rsqrtf(var + 1e-5f));
                }
            }
        }
        __syncthreads();
    };

    // ---- copy global A2 -> smem (stride LDA2) ----
    auto copy_A2 = [&](const unsigned short* gh, const unsigned short* gl) {
        for (int i = t; i < 2048; i += NTHR) {
            int row = i >> 5, seg = i & 31;
            long gr = rowBase + row;
            long grl = gr < N ? gr : (long)N - 1;
            uint4 vh = *reinterpret_cast<const uint4*>(gh + grl*256 + seg*8);
            uint4 vl = *reinterpret_cast<const uint4*>(gl + grl*256 + seg*8);
            *reinterpret_cast<uint4*>((char*)A_hi + row*528 + seg*16) = vh;
            *reinterpret_cast<uint4*>((char*)A_lo + row*528 + seg*16) = vl;
        }
        __syncthreads();
    };

    // ======== layer 1 (A1 shared by both towers) ========
    gemm(g_B1v, KT1, LDA1, sb + SM_A_HI, sb + SM_A_LO);
    epi_mid(g_S1v, g_c1v, g_A2v_hi, g_A2v_lo, stat2v);
    gemm(g_B1p, KT1, LDA1, sb + SM_A_HI, sb + SM_A_LO);
    epi_mid(g_S1p, g_c1p, g_A2p_hi, g_A2p_lo, stat2p);

    // ======== layer 2 value + value head ========
    copy_A2(g_A2v_hi, g_A2v_lo);
    gemm(g_B2v, KT2, LDA2, sb + SM_A_HI, sb + SM_A_LO);
    {
        float Sv[16], Cv[16], A3[16];
        #pragma unroll
        for (int nt = 0; nt < 8; nt++) {
            int n = ng*64 + nt*8 + qc*2;
            Sv[nt*2] = g_S2v[n]; Sv[nt*2+1] = g_S2v[n+1];
            Cv[nt*2] = g_c2v[n]; Cv[nt*2+1] = g_c2v[n+1];
            A3[nt*2] = g_a3v[n]; A3[nt*2+1] = g_a3v[n+1];
        }
        float4* vstat = (float4*)(smem + SM_SCRATCH);
        __syncthreads();   // statC reuse of SCRATCH done; safe to overwrite
        #pragma unroll
        for (int mt = 0; mt < 2; mt++) {
            const int rl = mg*32 + mt*16 + ql, rh = rl + 8;
            float2 stl = stat2v[rl], sth = stat2v[rh];
            float sl = 0.f, ssl = 0.f, vdl = 0.f, sh = 0.f, ssh = 0.f, vdh = 0.f;
            #pragma unroll
            for (int nt = 0; nt < 8; nt++) {
                float* d = c[mt][nt];
                float h00 = fmaxf(stl.y*(d[0] - stl.x*Sv[nt*2])   + Cv[nt*2],   0.f);
                float h01 = fmaxf(stl.y*(d[1] - stl.x*Sv[nt*2+1]) + Cv[nt*2+1], 0.f);
                float h10 = fmaxf(sth.y*(d[2] - sth.x*Sv[nt*2])   + Cv[nt*2],   0.f);
                float h11 = fmaxf(sth.y*(d[3] - sth.x*Sv[nt*2+1]) + Cv[nt*2+1], 0.f);
                sl += h00 + h01; ssl += h00*h00 + h01*h01;
                sh += h10 + h11; ssh += h10*h10 + h11*h11;
                vdl = fmaf(A3[nt*2], h00, fmaf(A3[nt*2+1], h01, vdl));
                vdh = fmaf(A3[nt*2], h10, fmaf(A3[nt*2+1], h11, vdh));
            }
            sl = qsum(sl); ssl = qsum(ssl); vdl = qsum(vdl);
            sh = qsum(sh); ssh = qsum(ssh); vdh = qsum(vdh);
            if (qc == 0) {
                vstat[rl*4 + ng] = make_float4(sl, ssl, vdl, 0.f);
                vstat[rh*4 + ng] = make_float4(sh, ssh, vdh, 0.f);
            }
        }
        __syncthreads();
        if (ng == 0 && qc == 0) {
            #pragma unroll
            for (int mt = 0; mt < 2; mt++) {
                #pragma unroll
                for (int hh = 0; hh < 2; hh++) {
                    int r = mg*32 + mt*16 + ql + hh*8;
                    float s = 0.f, ss = 0.f, vd = 0.f;
                    #pragma unroll
                    for (int g = 0; g < 4; g++) {
                        float4 v = vstat[r*4 + g];
                        s += v.x; ss += v.y; vd += v.z;
                    }
                    long gr = rowBase + r;
                    if (gr < N) {
                        const float inv = 1.f / (float)NH;
                        float m3 = s * inv;
                        float var3 = fmaxf(ss * inv - m3*m3, 0.f);
                        float rs3 = rsqrtf(var3 + 1e-5f);
                        out[gr] = rs3*(vd - m3*g_S3v) + g_c3v;
                    }
                }
            }
        }
        __syncthreads();
    }

    // ======== layer 2 prob + prob head (log_softmax) ========
    copy_A2(g_A2p_hi, g_A2p_lo);
    gemm(g_B2p, KT2, LDA2, sb + SM_A_HI, sb + SM_A_LO);
    {
        float Sv[16], Cv[16];
        #pragma unroll
        for (int nt = 0; nt < 8; nt++) {
            int n = ng*64 + nt*8 + qc*2;
            Sv[nt*2] = g_S2p[n]; Sv[nt*2+1] = g_S2p[n+1];
            Cv[nt*2] = g_c2p[n]; Cv[nt*2+1] = g_c2p[n+1];
        }
        float* pstat = (float*)(smem + SM_SCRATCH);   // [64][4][12]
        #pragma unroll
        for (int mt = 0; mt < 2; mt++) {
            const int rl = mg*32 + mt*16 + ql, rh = rl + 8;
            float2 stl = stat2p[rl], sth = stat2p[rh];
            float sl = 0.f, ssl = 0.f, sh = 0.f, ssh = 0.f;
            float Pl[10], Ph[10];
            #pragma unroll
            for (int q = 0; q < 10; q++) { Pl[q] = 0.f; Ph[q] = 0.f; }
            #pragma unroll
            for (int nt = 0; nt < 8; nt++) {
                int n = ng*64 + nt*8 + qc*2;
                float* d = c[mt][nt];
                float h00 = fmaxf(stl.y*(d[0] - stl.x*Sv[nt*2])   + Cv[nt*2],   0.f);
                float h01 = fmaxf(stl.y*(d[1] - stl.x*Sv[nt*2+1]) + Cv[nt*2+1], 0.f);
                float h10 = fmaxf(sth.y*(d[2] - sth.x*Sv[nt*2])   + Cv[nt*2],   0.f);
                float h11 = fmaxf(sth.y*(d[3] - sth.x*Sv[nt*2+1]) + Cv[nt*2+1], 0.f);
                sl += h00 + h01; ssl += h00*h00 + h01*h01;
                sh += h10 + h11; ssh += h10*h10 + h11*h11;
                const float* a0 = g_A3p + n*10;
                const float* a1 = a0 + 10;
                #pragma unroll
                for (int q = 0; q < 10; q++) {
                    Pl[q] = fmaf(h00, a0[q], fmaf(h01, a1[q], Pl[q]));
                    Ph[q] = fmaf(h10, a0[q], fmaf(h11, a1[q], Ph[q]));
                }
            }
            sl = qsum(sl); ssl = qsum(ssl); sh = qsum(sh); ssh = qsum(ssh);
            #pragma unroll
            for (int q = 0; q < 10; q++) { Pl[q] = qsum(Pl[q]); Ph[q] = qsum(Ph[q]); }
            if (qc == 0) {
                float* pl = pstat + (rl*4 + ng)*12;
                float* ph = pstat + (rh*4 + ng)*12;
                pl[0] = sl; pl[1] = ssl;
                ph[0] = sh; ph[1] = ssh;
                #pragma unroll
                for (int q = 0; q < 10; q++) { pl[2+q] = Pl[q]; ph[2+q] = Ph[q]; }
            }
        }
        __syncthreads();
        if (ng == 0 && qc == 0) {
            #pragma unroll
            for (int mt = 0; mt < 2; mt++) {
                #pragma unroll
                for (int hh = 0; hh < 2; hh++) {
                    int r = mg*32 + mt*16 + ql + hh*8;
                    float s = 0.f, ss = 0.f;
                    float P[10];
                    #pragma unroll
                    for (int q = 0; q < 10; q++) P[q] = 0.f;
                    #pragma unroll
                    for (int g = 0; g < 4; g++) {
                        const float* v = pstat + (r*4 + g)*12;
                        s += v[0]; ss += v[1];
                        #pragma unroll
                        for (int q = 0; q < 10; q++) P[q] += v[2+q];
                    }
                    long gr = rowBase + r;
                    if (gr < N) {
                        const float inv = 1.f / (float)NH;
                        float m3 = s * inv;
                        float var3 = fmaxf(ss * inv - m3*m3, 0.f);
                        float rs3 = rsqrtf(var3 + 1e-5f);
                        float sc[10];
                        float mx = -3.4e38f;
                        #pragma unroll
                        for (int q = 0; q < 10; q++) {
                            sc[q] = rs3*(P[q] - m3*g_S3p[q]) + g_c3p[q];
                            mx = fmaxf(mx, sc[q]);
                        }
                        float se = 0.f;
                        #pragma unroll
                        for (int q = 0; q < 10; q++) se += expf(sc[q] - mx);
                        float lse = mx + logf(se);
                        float* lp = out + N + gr * 10;
                        float* so = out + N + (long)N * 10 + gr * 10;
                        #pragma unroll
                        for (int q = 0; q < 10; q++) {
                            lp[q] = sc[q] - lse;
                            so[q] = sc[q];
                        }
                    }
                }
            }
        }
    }
}

// ===========================================================================
extern "C" void kernel_launch(void* const* d_in, const int* in_sizes, int n_in,
                              void* d_out, int out_size) {
    const float* cum  = (const float*)d_in[0];
    const float* feat = (const float*)d_in[1];
    const float* pos  = (const float*)d_in[2];
    const int N = in_sizes[0] / 146;

    cudaFuncSetAttribute(bcq_mma, cudaFuncAttributeMaxDynamicSharedMemorySize, SMEM_TOTAL);

    prep1<<<512, 320>>>(
        (const float*)d_in[3],  (const float*)d_in[4],    // ln1_w, ln1_b
        (const float*)d_in[9],  (const float*)d_in[10],   // norm1_g, norm1_b
        (const float*)d_in[15], (const float*)d_in[16],   // prob1_w, prob1_b
        (const float*)d_in[21], (const float*)d_in[22]);  // pnorm1_g, pnorm1_b
    prep2<<<512, 256>>>(
        (const float*)d_in[5],  (const float*)d_in[6],    // ln2_w, ln2_b
        (const float*)d_in[11], (const float*)d_in[12],   // norm2_g, norm2_b
        (const float*)d_in[17], (const float*)d_in[18],   // prob2_w, prob2_b
        (const float*)d_in[23], (const float*)d_in[24]);  // pnorm2_g, pnorm2_b
    prep3<<<1, 256>>>(
        (const float*)d_in[7],  (const float*)d_in[8],    // ln3_w, ln3_b
        (const float*)d_in[13], (const float*)d_in[14],   // norm3_g, norm3_b
        (const float*)d_in[19], (const float*)d_in[20],   // prob3_w, prob3_b
        (const float*)d_in[25], (const float*)d_in[26]);  // pnorm3_g, pnorm3_b

    const int grid = (N + MROWS - 1) / MROWS;
    bcq_mma<<<grid, NTHR, SMEM_TOTAL>>>(cum, feat, pos, (float*)d_out, N);
}

// round 15
// speedup vs baseline: 2.2568x; 1.2816x over previous
#include <cuda_runtime.h>
#include <cuda_fp16.h>
#include <cstdint>

#define MAXN   (1<<17)
#define K1     292
#define KT1    19           // layer1 k16-chunks (covers 304; 292..303 zero-pad)
#define LDA1   328          // A1 smem row stride (elems) = 656B
#define KT2    16
#define LDA2   264          // A2 smem row stride = 528B
#define NH     256
#define MROWS  64
#define NTHR   256

// smem byte offsets (total 55808 -> 2 CTAs/SM, regs-limited)
#define SM_A       0                 // 64*328*2 = 41984
#define SM_SCRATCH 41984             // 12288: statC / vstat / pstat (time-shared)
#define SM_STAT1   54272             // 64 x float2
#define SM_STAT2V  54784
#define SM_STAT2P  55296
#define SMEM_TOTAL 55808

// ===========================================================================
// fp16 weight images in mma-fragment order, n-tile pairs packed per uint4:
//   uint4 idx = (ch*16 + jp)*32 + lane,  jp = (n>>3)>>1, lane = (n&7)*4+((k&7)>>1)
//   sub = (n>>3)&1: 0 -> {.x=b0,.y=b1}, 1 -> {.z=b0,.w=b1}; 16-bit half = k&1
// ===========================================================================
__device__ __align__(16) uint4 g_B1v[KT1*512], g_B1p[KT1*512];
__device__ __align__(16) uint4 g_B2v[KT2*512], g_B2p[KT2*512];

__device__ float g_S1v[NH], g_S1p[NH], g_c1v[NH], g_c1p[NH];
__device__ float g_S2v[NH], g_S2p[NH], g_c2v[NH], g_c2p[NH];
__device__ float g_a3v[NH];
__device__ float g_A3p[NH*10];
__device__ float g_S3v, g_c3v;
__device__ float g_S3p[10], g_c3p[10];

__device__ __align__(16) unsigned short g_A2v[(size_t)MAXN*256];
__device__ __align__(16) unsigned short g_A2p[(size_t)MAXN*256];

// ===========================================================================
// helpers
// ===========================================================================
__device__ __forceinline__ unsigned short f2h(float x) {
    __half h = __float2half(x);
    return *reinterpret_cast<unsigned short*>(&h);
}
__device__ __forceinline__ uint32_t smem_u32(const void* p) {
    uint32_t a;
    asm("{ .reg .u64 t; cvta.to.shared.u64 t, %1; cvt.u32.u64 %0, t; }"
        : "=r"(a) : "l"(p));
    return a;
}
__device__ __forceinline__ void ldsm_x4(uint32_t addr, uint32_t* r) {
    asm volatile("ldmatrix.sync.aligned.m8n8.x4.shared.b16 {%0,%1,%2,%3}, [%4];"
        : "=r"(r[0]), "=r"(r[1]), "=r"(r[2]), "=r"(r[3]) : "r"(addr));
}
__device__ __forceinline__ void mma_f16(float* c, const uint32_t* a, uint32_t b0, uint32_t b1) {
    asm volatile(
        "mma.sync.aligned.m16n8k16.row.col.f32.f16.f16.f32 "
        "{%0,%1,%2,%3}, {%4,%5,%6,%7}, {%8,%9}, {%0,%1,%2,%3};"
        : "+f"(c[0]), "+f"(c[1]), "+f"(c[2]), "+f"(c[3])
        : "r"(a[0]), "r"(a[1]), "r"(a[2]), "r"(a[3]), "r"(b0), "r"(b1));
}
__device__ __forceinline__ float qsum(float v) {
    v += __shfl_xor_sync(0xffffffffu, v, 1);
    v += __shfl_xor_sync(0xffffffffu, v, 2);
    return v;
}

// fragment-order ushort index for fp16 image
__device__ __forceinline__ size_t bimg_us(int n, int k) {
    int ch = k >> 4;
    int jp = (n >> 3) >> 1, sub = (n >> 3) & 1;
    int lane = ((n & 7) << 2) | ((k & 7) >> 1);
    int reg = (k >> 3) & 1, half = k & 1;
    return (((size_t)(ch*16 + jp)*32 + lane) * 8) + sub*4 + reg*2 + half;
}

// ===========================================================================
// Prep kernels
// ===========================================================================
__global__ void prep1(const float* __restrict__ ln1_w, const float* __restrict__ ln1_b,
                      const float* __restrict__ n1g,  const float* __restrict__ n1b,
                      const float* __restrict__ p1w,  const float* __restrict__ p1b,
                      const float* __restrict__ pn1g, const float* __restrict__ pn1b)
{
    __shared__ float rs[10], rc[10];
    const int tower = blockIdx.x >> 8, n = blockIdx.x & 255, k = threadIdx.x;
    const int wid = k >> 5, lane = k & 31;
    const float* W  = tower ? p1w  : ln1_w;
    const float* bi = tower ? p1b  : ln1_b;
    const float* g  = tower ? pn1g : n1g;
    const float* be = tower ? pn1b : n1b;
    unsigned short* img = (unsigned short*)(tower ? g_B1p : g_B1v);

    float wg = 0.f, wb = 0.f;
    if (k < K1) {
        float w = W[n*K1 + k];
        wg = w * g[k];
        wb = w * be[k];
    }
    if (k < KT1*16)
        img[bimg_us(n, k)] = f2h(wg);
    #pragma unroll
    for (int o = 16; o; o >>= 1) {
        wg += __shfl_xor_sync(0xffffffffu, wg, o);
        wb += __shfl_xor_sync(0xffffffffu, wb, o);
    }
    if (lane == 0) { rs[wid] = wg; rc[wid] = wb; }
    __syncthreads();
    if (k == 0) {
        float S = 0.f, C = 0.f;
        for (int i = 0; i < 10; i++) { S += rs[i]; C += rc[i]; }
        (tower ? g_S1p : g_S1v)[n] = S;
        (tower ? g_c1p : g_c1v)[n] = bi[n] + C;
    }
}

__global__ void prep2(const float* __restrict__ ln2_w, const float* __restrict__ ln2_b,
                      const float* __restrict__ n2g,  const float* __restrict__ n2b,
                      const float* __restrict__ p2w,  const float* __restrict__ p2b,
                      const float* __restrict__ pn2g, const float* __restrict__ pn2b)
{
    __shared__ float rs[8], rc[8];
    const int tower = blockIdx.x >> 8, n = blockIdx.x & 255, k = threadIdx.x;
    const int wid = k >> 5, lane = k & 31;
    const float* W  = tower ? p2w  : ln2_w;
    const float* bi = tower ? p2b  : ln2_b;
    const float* g  = tower ? pn2g : n2g;
    const float* be = tower ? pn2b : n2b;
    unsigned short* img = (unsigned short*)(tower ? g_B2p : g_B2v);

    float w  = W[n*NH + k];
    float wg = w * g[k];
    float wb = w * be[k];
    img[bimg_us(n, k)] = f2h(wg);
    #pragma unroll
    for (int o = 16; o; o >>= 1) {
        wg += __shfl_xor_sync(0xffffffffu, wg, o);
        wb += __shfl_xor_sync(0xffffffffu, wb, o);
    }
    if (lane == 0) { rs[wid] = wg; rc[wid] = wb; }
    __syncthreads();
    if (k == 0) {
        float S = 0.f, C = 0.f;
        for (int i = 0; i < 8; i++) { S += rs[i]; C += rc[i]; }
        (tower ? g_S2p : g_S2v)[n] = S;
        (tower ? g_c2p : g_c2v)[n] = bi[n] + C;
    }
}

__global__ void prep3(const float* __restrict__ ln3_w, const float* __restrict__ ln3_b,
                      const float* __restrict__ n3g,  const float* __restrict__ n3b,
                      const float* __restrict__ p3w,  const float* __restrict__ p3b,
                      const float* __restrict__ pn3g, const float* __restrict__ pn3b)
{
    const int n = threadIdx.x;
    g_a3v[n] = ln3_w[n] * n3g[n];
    #pragma unroll
    for (int j = 0; j < 10; j++)
        g_A3p[n*10 + j] = p3w[j*NH + n] * pn3g[n];
    __syncthreads();
    if (n == 0) {
        float S = 0.f, C = 0.f;
        for (int k = 0; k < NH; k++) { S += g_a3v[k]; C += ln3_w[k] * n3b[k]; }
        g_S3v = S; g_c3v = ln3_b[0] + C;
    }
    if (n >= 1 && n <= 10) {
        int j = n - 1;
        float S = 0.f, C = 0.f;
        for (int k = 0; k < NH; k++) { S += g_A3p[k*10 + j]; C += p3w[j*NH + k] * pn3b[k]; }
        g_S3p[j] = S; g_c3p[j] = p3b[j] + C;
    }
}

// ===========================================================================
// Main kernel: 64 rows/CTA, warp tile 32x64, fp16 single MMA,
// B LDG.128 from L2 (fragment order) with register double-buffer
// ===========================================================================
__global__ __launch_bounds__(NTHR, 2)
void bcq_mma(const float* __restrict__ cum, const float* __restrict__ feat,
             const float* __restrict__ pos, float* __restrict__ out, int N)
{
    extern __shared__ char smem[];
    const uint32_t sb = smem_u32(smem);
    const int t = threadIdx.x, wid = t >> 5, l = t & 31;
    const int mg = wid >> 2, ng = wid & 3;          // rows mg*32+, cols ng*64+
    const int ql = l >> 2, qc = l & 3;
    const long rowBase = (long)blockIdx.x * MROWS;

    float2* stat1  = (float2*)(smem + SM_STAT1);
    float2* statC  = (float2*)(smem + SM_SCRATCH);
    float2* stat2v = (float2*)(smem + SM_STAT2V);
    float2* stat2p = (float2*)(smem + SM_STAT2P);
    unsigned short* A_sm = (unsigned short*)(smem + SM_A);

    // ---- zero A region (layer1 k-pad 292..303 must be 0) ----
    {
        uint4 z; z.x = z.y = z.z = z.w = 0;
        uint4* a4 = (uint4*)smem;
        for (int i = t; i < 41984/16; i += NTHR) a4[i] = z;
    }
    __syncthreads();

    // ---- phase 1: x -> A1 fp16 smem + LN1 stats ----
    {
        const int row = t >> 2, q = t & 3;
        long gr = rowBase + row;
        long grl = gr < N ? gr : (long)N - 1;
        const float* c0 = cum  + grl * 146;
        const float* f0 = feat + grl * 136;
        const float* p0 = pos  + grl * 10;
        float s = 0.f, ss = 0.f;
        for (int k = q*73; k < q*73 + 73; k++) {
            float x = (k < 146) ? c0[k] : (k < 282 ? f0[k-146] : p0[k-282]);
            s += x; ss += x*x;
            A_sm[row*LDA1 + k] = f2h(x);
        }
        s = qsum(s); ss = qsum(ss);
        if (q == 0) {
            const float inv = 1.f / (float)K1;
            float m = s * inv;
            float var = fmaxf(ss * inv - m*m, 0.f);
            stat1[row] = make_float2(m, rsqrtf(var + 1e-5f));
        }
    }
    __syncthreads();

    float c[2][8][4];

    // ---- GEMM: B from L2 in fragment order, double-buffered in regs ----
    auto gemm = [&](const uint4* __restrict__ Bimg, int KT, int lda, uint32_t aSm) {
        #pragma unroll
        for (int mt = 0; mt < 2; mt++)
            #pragma unroll
            for (int nt = 0; nt < 8; nt++)
                #pragma unroll
                for (int i = 0; i < 4; i++) c[mt][nt][i] = 0.f;

        const int arow = l & 15, akh = l >> 4;
        const uint4* Bp = Bimg + (size_t)(ng*4)*32 + l;

        uint4 bc[4], bn[4];
        #pragma unroll
        for (int j = 0; j < 4; j++) bc[j] = Bp[j*32];

        #pragma unroll 1
        for (int ch = 0; ch < KT; ch++) {
            if (ch + 1 < KT) {
                #pragma unroll
                for (int j = 0; j < 4; j++) bn[j] = Bp[((ch+1)*16 + j)*32];
            }
            uint32_t ah[2][4];
            #pragma unroll
            for (int mt = 0; mt < 2; mt++) {
                uint32_t ao = (uint32_t)(((mg*32 + mt*16 + arow)*lda + ch*16 + akh*8) * 2);
                ldsm_x4(aSm + ao, ah[mt]);
            }
            #pragma unroll
            for (int nt = 0; nt < 8; nt++) {
                uint32_t b0 = (nt & 1) ? bc[nt>>1].z : bc[nt>>1].x;
                uint32_t b1 = (nt & 1) ? bc[nt>>1].w : bc[nt>>1].y;
                mma_f16(c[0][nt], ah[0], b0, b1);
                mma_f16(c[1][nt], ah[1], b0, b1);
            }
            #pragma unroll
            for (int j = 0; j < 4; j++) bc[j] = bn[j];
        }
    };

    // ---- mid epilogue: D -> h(relu) -> global A2 fp16; LN2 stats -> stat2 ----
    auto epi_mid = [&](const float* Sg, const float* cvg,
                       unsigned short* gA2, float2* stat2) {
        float Sv[16], Cv[16];
        #pragma unroll
        for (int nt = 0; nt < 8; nt++) {
            int n = ng*64 + nt*8 + qc*2;
            Sv[nt*2]   = Sg[n];   Sv[nt*2+1] = Sg[n+1];
            Cv[nt*2]   = cvg[n];  Cv[nt*2+1] = cvg[n+1];
        }
        #pragma unroll
        for (int mt = 0; mt < 2; mt++) {
            const int rl = mg*32 + mt*16 + ql, rh = rl + 8;
            float2 stl = stat1[rl], sth = stat1[rh];
            float sl = 0.f, ssl = 0.f, sh = 0.f, ssh = 0.f;
            #pragma unroll
            for (int nt = 0; nt < 8; nt++) {
                int n = ng*64 + nt*8 + qc*2;
                float* d = c[mt][nt];
                float h00 = fmaxf(stl.y*(d[0] - stl.x*Sv[nt*2])   + Cv[nt*2],   0.f);
                float h01 = fmaxf(stl.y*(d[1] - stl.x*Sv[nt*2+1]) + Cv[nt*2+1], 0.f);
                float h10 = fmaxf(sth.y*(d[2] - sth.x*Sv[nt*2])   + Cv[nt*2],   0.f);
                float h11 = fmaxf(sth.y*(d[3] - sth.x*Sv[nt*2+1]) + Cv[nt*2+1], 0.f);
                sl += h00 + h01; ssl += h00*h00 + h01*h01;
                sh += h10 + h11; ssh += h10*h10 + h11*h11;
                long grl = rowBase + rl, grh = rowBase + rh;
                if (grl < N)
                    *(uint32_t*)(gA2 + grl*256 + n) = (uint32_t)f2h(h00) | ((uint32_t)f2h(h01) << 16);
                if (grh < N)
                    *(uint32_t*)(gA2 + grh*256 + n) = (uint32_t)f2h(h10) | ((uint32_t)f2h(h11) << 16);
            }
            sl = qsum(sl); ssl = qsum(ssl); sh = qsum(sh); ssh = qsum(ssh);
            if (qc == 0) {
                statC[rl*4 + ng] = make_float2(sl, ssl);
                statC[rh*4 + ng] = make_float2(sh, ssh);
            }
        }
        __syncthreads();
        if (ng == 0 && qc == 0) {
            #pragma unroll
            for (int mt = 0; mt < 2; mt++) {
                #pragma unroll
                for (int hh = 0; hh < 2; hh++) {
                    int r = mg*32 + mt*16 + ql + hh*8;
                    float s = 0.f, ss = 0.f;
                    #pragma unroll
                    for (int g = 0; g < 4; g++) {
                        float2 v = statC[r*4 + g];
                        s += v.x; ss += v.y;
                    }
                    const float inv = 1.f / (float)NH;
                    float m = s * inv;
                    float var = fmaxf(ss * inv - m*m, 0.f);
                    stat2[r] = make_float2(m, rsqrtf(var + 1e-5f));
                }
            }
        }
        __syncthreads();
    };

    // ---- copy global A2 -> smem (stride LDA2) ----
    auto copy_A2 = [&](const unsigned short* gA2) {
        for (int i = t; i < 2048; i += NTHR) {
            int row = i >> 5, seg = i & 31;
            long gr = rowBase + row;
            long grl = gr < N ? gr : (long)N - 1;
            uint4 v = *reinterpret_cast<const uint4*>(gA2 + grl*256 + seg*8);
            *reinterpret_cast<uint4*>((char*)A_sm + row*528 + seg*16) = v;
        }
        __syncthreads();
    };

    // ======== layer 1 (A1 shared by both towers) ========
    gemm(g_B1v, KT1, LDA1, sb + SM_A);
    epi_mid(g_S1v, g_c1v, g_A2v, stat2v);
    gemm(g_B1p, KT1, LDA1, sb + SM_A);
    epi_mid(g_S1p, g_c1p, g_A2p, stat2p);

    // ======== layer 2 value + value head ========
    copy_A2(g_A2v);
    gemm(g_B2v, KT2, LDA2, sb + SM_A);
    {
        float Sv[16], Cv[16], A3[16];
        #pragma unroll
        for (int nt = 0; nt < 8; nt++) {
            int n = ng*64 + nt*8 + qc*2;
            Sv[nt*2] = g_S2v[n]; Sv[nt*2+1] = g_S2v[n+1];
            Cv[nt*2] = g_c2v[n]; Cv[nt*2+1] = g_c2v[n+1];
            A3[nt*2] = g_a3v[n]; A3[nt*2+1] = g_a3v[n+1];
        }
        float4* vstat = (float4*)(smem + SM_SCRATCH);
        #pragma unroll
        for (int mt = 0; mt < 2; mt++) {
            const int rl = mg*32 + mt*16 + ql, rh = rl + 8;
            float2 stl = stat2v[rl], sth = stat2v[rh];
            float sl = 0.f, ssl = 0.f, vdl = 0.f, sh = 0.f, ssh = 0.f, vdh = 0.f;
            #pragma unroll
            for (int nt = 0; nt < 8; nt++) {
                float* d = c[mt][nt];
                float h00 = fmaxf(stl.y*(d[0] - stl.x*Sv[nt*2])   + Cv[nt*2],   0.f);
                float h01 = fmaxf(stl.y*(d[1] - stl.x*Sv[nt*2+1]) + Cv[nt*2+1], 0.f);
                float h10 = fmaxf(sth.y*(d[2] - sth.x*Sv[nt*2])   + Cv[nt*2],   0.f);
                float h11 = fmaxf(sth.y*(d[3] - sth.x*Sv[nt*2+1]) + Cv[nt*2+1], 0.f);
                sl += h00 + h01; ssl += h00*h00 + h01*h01;
                sh += h10 + h11; ssh += h10*h10 + h11*h11;
                vdl = fmaf(A3[nt*2], h00, fmaf(A3[nt*2+1], h01, vdl));
                vdh = fmaf(A3[nt*2], h10, fmaf(A3[nt*2+1], h11, vdh));
            }
            sl = qsum(sl); ssl = qsum(ssl); vdl = qsum(vdl);
            sh = qsum(sh); ssh = qsum(ssh); vdh = qsum(vdh);
            if (qc == 0) {
                vstat[rl*4 + ng] = make_float4(sl, ssl, vdl, 0.f);
                vstat[rh*4 + ng] = make_float4(sh, ssh, vdh, 0.f);
            }
        }
        __syncthreads();
        if (ng == 0 && qc == 0) {
            #pragma unroll
            for (int mt = 0; mt < 2; mt++) {
                #pragma unroll
                for (int hh = 0; hh < 2; hh++) {
                    int r = mg*32 + mt*16 + ql + hh*8;
                    float s = 0.f, ss = 0.f, vd = 0.f;
                    #pragma unroll
                    for (int g = 0; g < 4; g++) {
                        float4 v = vstat[r*4 + g];
                        s += v.x; ss += v.y; vd += v.z;
                    }
                    long gr = rowBase + r;
                    if (gr < N) {
                        const float inv = 1.f / (float)NH;
                        float m3 = s * inv;
                        float var3 = fmaxf(ss * inv - m3*m3, 0.f);
                        float rs3 = rsqrtf(var3 + 1e-5f);
                        out[gr] = rs3*(vd - m3*g_S3v) + g_c3v;
                    }
                }
            }
        }
        __syncthreads();
    }

    // ======== layer 2 prob + prob head (log_softmax) ========
    copy_A2(g_A2p);
    gemm(g_B2p, KT2, LDA2, sb + SM_A);
    {
        float Sv[16], Cv[16];
        #pragma unroll
        for (int nt = 0; nt < 8; nt++) {
            int n = ng*64 + nt*8 + qc*2;
            Sv[nt*2] = g_S2p[n]; Sv[nt*2+1] = g_S2p[n+1];
            Cv[nt*2] = g_c2p[n]; Cv[nt*2+1] = g_c2p[n+1];
        }
        float* pstat = (float*)(smem + SM_SCRATCH);   // [64][4][12]
        #pragma unroll
        for (int mt = 0; mt < 2; mt++) {
            const int rl = mg*32 + mt*16 + ql, rh = rl + 8;
            float2 stl = stat2p[rl], sth = stat2p[rh];
            float sl = 0.f, ssl = 0.f, sh = 0.f, ssh = 0.f;
            float Pl[10], Ph[10];
            #pragma unroll
            for (int q = 0; q < 10; q++) { Pl[q] = 0.f; Ph[q] = 0.f; }
            #pragma unroll
            for (int nt = 0; nt < 8; nt++) {
                int n = ng*64 + nt*8 + qc*2;
                float* d = c[mt][nt];
                float h00 = fmaxf(stl.y*(d[0] - stl.x*Sv[nt*2])   + Cv[nt*2],   0.f);
                float h01 = fmaxf(stl.y*(d[1] - stl.x*Sv[nt*2+1]) + Cv[nt*2+1], 0.f);
                float h10 = fmaxf(sth.y*(d[2] - sth.x*Sv[nt*2])   + Cv[nt*2],   0.f);
                float h11 = fmaxf(sth.y*(d[3] - sth.x*Sv[nt*2+1]) + Cv[nt*2+1], 0.f);
                sl += h00 + h01; ssl += h00*h00 + h01*h01;
                sh += h10 + h11; ssh += h10*h10 + h11*h11;
                const float* a0 = g_A3p + n*10;
                const float* a1 = a0 + 10;
                #pragma unroll
                for (int q = 0; q < 10; q++) {
                    Pl[q] = fmaf(h00, a0[q], fmaf(h01, a1[q], Pl[q]));
                    Ph[q] = fmaf(h10, a0[q], fmaf(h11, a1[q], Ph[q]));
                }
            }
            sl = qsum(sl); ssl = qsum(ssl); sh = qsum(sh); ssh = qsum(ssh);
            #pragma unroll
            for (int q = 0; q < 10; q++) { Pl[q] = qsum(Pl[q]); Ph[q] = qsum(Ph[q]); }
            if (qc == 0) {
                float* pl = pstat + (rl*4 + ng)*12;
                float* ph = pstat + (rh*4 + ng)*12;
                pl[0] = sl; pl[1] = ssl;
                ph[0] = sh; ph[1] = ssh;
                #pragma unroll
                for (int q = 0; q < 10; q++) { pl[2+q] = Pl[q]; ph[2+q] = Ph[q]; }
            }
        }
        __syncthreads();
        if (ng == 0 && qc == 0) {
            #pragma unroll
            for (int mt = 0; mt < 2; mt++) {
                #pragma unroll
                for (int hh = 0; hh < 2; hh++) {
                    int r = mg*32 + mt*16 + ql + hh*8;
                    float s = 0.f, ss = 0.f;
                    float P[10];
                    #pragma unroll
                    for (int q = 0; q < 10; q++) P[q] = 0.f;
                    #pragma unroll
                    for (int g = 0; g < 4; g++) {
                        const float* v = pstat + (r*4 + g)*12;
                        s += v[0]; ss += v[1];
                        #pragma unroll
                        for (int q = 0; q < 10; q++) P[q] += v[2+q];
                    }
                    long gr = rowBase + r;
                    if (gr < N) {
                        const float inv = 1.f / (float)NH;
                        float m3 = s * inv;
                        float var3 = fmaxf(ss * inv - m3*m3, 0.f);
                        float rs3 = rsqrtf(var3 + 1e-5f);
                        float sc[10];
                        float mx = -3.4e38f;
                        #pragma unroll
                        for (int q = 0; q < 10; q++) {
                            sc[q] = rs3*(P[q] - m3*g_S3p[q]) + g_c3p[q];
                            mx = fmaxf(mx, sc[q]);
                        }
                        float se = 0.f;
                        #pragma unroll
                        for (int q = 0; q < 10; q++) se += expf(sc[q] - mx);
                        float lse = mx + logf(se);
                        float* lp = out + N + gr * 10;
                        float* so = out + N + (long)N * 10 + gr * 10;
                        #pragma unroll
                        for (int q = 0; q < 10; q++) {
                            lp[q] = sc[q] - lse;
                            so[q] = sc[q];
                        }
                    }
                }
            }
        }
    }
}

// ===========================================================================
extern "C" void kernel_launch(void* const* d_in, const int* in_sizes, int n_in,
                              void* d_out, int out_size) {
    const float* cum  = (const float*)d_in[0];
    const float* feat = (const float*)d_in[1];
    const float* pos  = (const float*)d_in[2];
    const int N = in_sizes[0] / 146;

    cudaFuncSetAttribute(bcq_mma, cudaFuncAttributeMaxDynamicSharedMemorySize, SMEM_TOTAL);

    prep1<<<512, 320>>>(
        (const float*)d_in[3],  (const float*)d_in[4],    // ln1_w, ln1_b
        (const float*)d_in[9],  (const float*)d_in[10],   // norm1_g, norm1_b
        (const float*)d_in[15], (const float*)d_in[16],   // prob1_w, prob1_b
        (const float*)d_in[21], (const float*)d_in[22]);  // pnorm1_g, pnorm1_b
    prep2<<<512, 256>>>(
        (const float*)d_in[5],  (const float*)d_in[6],    // ln2_w, ln2_b
        (const float*)d_in[11], (const float*)d_in[12],   // norm2_g, norm2_b
        (const float*)d_in[17], (const float*)d_in[18],   // prob2_w, prob2_b
        (const float*)d_in[23], (const float*)d_in[24]);  // pnorm2_g, pnorm2_b
    prep3<<<1, 256>>>(
        (const float*)d_in[7],  (const float*)d_in[8],    // ln3_w, ln3_b
        (const float*)d_in[13], (const float*)d_in[14],   // norm3_g, norm3_b
        (const float*)d_in[19], (const float*)d_in[20],   // prob3_w, prob3_b
        (const float*)d_in[25], (const float*)d_in[26]);  // pnorm3_g, pnorm3_b

    const int grid = (N + MROWS - 1) / MROWS;
    bcq_mma<<<grid, NTHR, SMEM_TOTAL>>>(cum, feat, pos, (float*)d_out, N);
}

// round 16
// speedup vs baseline: 2.7079x; 1.1999x over previous
#include <cuda_runtime.h>
#include <cuda_fp16.h>
#include <cstdint>

#define K1     292
#define KT1    19           // layer1 k16-chunks (covers 304; 292..303 zero-pad)
#define LDA1   328          // A1 smem row stride (elems) = 656B
#define KT2    16
#define LDA2   264          // A2 smem row stride = 528B
#define NH     256
#define MROWS  64
#define NTHR   256

// smem byte offsets (total 89088 -> 2 CTAs/SM)
#define SM_A1      0                 // 64*328*2 = 41984
#define SM_A2      41984             // 64*264*2 = 33792
#define SM_SCRATCH 75776             // 12288: statC / vstat / pstat (time-shared)
#define SM_STAT1   88064             // 64 x float2
#define SM_STAT2   88576             // 64 x float2 (reused per tower)
#define SMEM_TOTAL 89088

// ===========================================================================
// fp16 weight images in mma-fragment order, n-tile pairs packed per uint4:
//   uint4 idx = (ch*16 + jp)*32 + lane,  jp = (n>>3)>>1, lane = (n&7)*4+((k&7)>>1)
//   sub = (n>>3)&1: 0 -> {.x=b0,.y=b1}, 1 -> {.z=b0,.w=b1}; 16-bit half = k&1
// ===========================================================================
__device__ __align__(16) uint4 g_B1v[KT1*512], g_B1p[KT1*512];
__device__ __align__(16) uint4 g_B2v[KT2*512], g_B2p[KT2*512];

__device__ float g_S1v[NH], g_S1p[NH], g_c1v[NH], g_c1p[NH];
__device__ float g_S2v[NH], g_S2p[NH], g_c2v[NH], g_c2p[NH];
__device__ float g_a3v[NH];
__device__ float g_A3p[NH*10];
__device__ float g_S3v, g_c3v;
__device__ float g_S3p[10], g_c3p[10];

// ===========================================================================
// helpers
// ===========================================================================
__device__ __forceinline__ unsigned short f2h(float x) {
    __half h = __float2half(x);
    return *reinterpret_cast<unsigned short*>(&h);
}
__device__ __forceinline__ uint32_t smem_u32(const void* p) {
    uint32_t a;
    asm("{ .reg .u64 t; cvta.to.shared.u64 t, %1; cvt.u32.u64 %0, t; }"
        : "=r"(a) : "l"(p));
    return a;
}
__device__ __forceinline__ void ldsm_x4(uint32_t addr, uint32_t* r) {
    asm volatile("ldmatrix.sync.aligned.m8n8.x4.shared.b16 {%0,%1,%2,%3}, [%4];"
        : "=r"(r[0]), "=r"(r[1]), "=r"(r[2]), "=r"(r[3]) : "r"(addr));
}
__device__ __forceinline__ void mma_f16(float* c, const uint32_t* a, uint32_t b0, uint32_t b1) {
    asm volatile(
        "mma.sync.aligned.m16n8k16.row.col.f32.f16.f16.f32 "
        "{%0,%1,%2,%3}, {%4,%5,%6,%7}, {%8,%9}, {%0,%1,%2,%3};"
        : "+f"(c[0]), "+f"(c[1]), "+f"(c[2]), "+f"(c[3])
        : "r"(a[0]), "r"(a[1]), "r"(a[2]), "r"(a[3]), "r"(b0), "r"(b1));
}
__device__ __forceinline__ float qsum(float v) {
    v += __shfl_xor_sync(0xffffffffu, v, 1);
    v += __shfl_xor_sync(0xffffffffu, v, 2);
    return v;
}

// fragment-order ushort index for fp16 image
__device__ __forceinline__ size_t bimg_us(int n, int k) {
    int ch = k >> 4;
    int jp = (n >> 3) >> 1, sub = (n >> 3) & 1;
    int lane = ((n & 7) << 2) | ((k & 7) >> 1);
    int reg = (k >> 3) & 1, half = k & 1;
    return (((size_t)(ch*16 + jp)*32 + lane) * 8) + sub*4 + reg*2 + half;
}

// ===========================================================================
// Prep kernels
// ===========================================================================
__global__ void prep1(const float* __restrict__ ln1_w, const float* __restrict__ ln1_b,
                      const float* __restrict__ n1g,  const float* __restrict__ n1b,
                      const float* __restrict__ p1w,  const float* __restrict__ p1b,
                      const float* __restrict__ pn1g, const float* __restrict__ pn1b)
{
    __shared__ float rs[10], rc[10];
    const int tower = blockIdx.x >> 8, n = blockIdx.x & 255, k = threadIdx.x;
    const int wid = k >> 5, lane = k & 31;
    const float* W  = tower ? p1w  : ln1_w;
    const float* bi = tower ? p1b  : ln1_b;
    const float* g  = tower ? pn1g : n1g;
    const float* be = tower ? pn1b : n1b;
    unsigned short* img = (unsigned short*)(tower ? g_B1p : g_B1v);

    float wg = 0.f, wb = 0.f;
    if (k < K1) {
        float w = W[n*K1 + k];
        wg = w * g[k];
        wb = w * be[k];
    }
    if (k < KT1*16)
        img[bimg_us(n, k)] = f2h(wg);
    #pragma unroll
    for (int o = 16; o; o >>= 1) {
        wg += __shfl_xor_sync(0xffffffffu, wg, o);
        wb += __shfl_xor_sync(0xffffffffu, wb, o);
    }
    if (lane == 0) { rs[wid] = wg; rc[wid] = wb; }
    __syncthreads();
    if (k == 0) {
        float S = 0.f, C = 0.f;
        for (int i = 0; i < 10; i++) { S += rs[i]; C += rc[i]; }
        (tower ? g_S1p : g_S1v)[n] = S;
        (tower ? g_c1p : g_c1v)[n] = bi[n] + C;
    }
}

__global__ void prep2(const float* __restrict__ ln2_w, const float* __restrict__ ln2_b,
                      const float* __restrict__ n2g,  const float* __restrict__ n2b,
                      const float* __restrict__ p2w,  const float* __restrict__ p2b,
                      const float* __restrict__ pn2g, const float* __restrict__ pn2b)
{
    __shared__ float rs[8], rc[8];
    const int tower = blockIdx.x >> 8, n = blockIdx.x & 255, k = threadIdx.x;
    const int wid = k >> 5, lane = k & 31;
    const float* W  = tower ? p2w  : ln2_w;
    const float* bi = tower ? p2b  : ln2_b;
    const float* g  = tower ? pn2g : n2g;
    const float* be = tower ? pn2b : n2b;
    unsigned short* img = (unsigned short*)(tower ? g_B2p : g_B2v);

    float w  = W[n*NH + k];
    float wg = w * g[k];
    float wb = w * be[k];
    img[bimg_us(n, k)] = f2h(wg);
    #pragma unroll
    for (int o = 16; o; o >>= 1) {
        wg += __shfl_xor_sync(0xffffffffu, wg, o);
        wb += __shfl_xor_sync(0xffffffffu, wb, o);
    }
    if (lane == 0) { rs[wid] = wg; rc[wid] = wb; }
    __syncthreads();
    if (k == 0) {
        float S = 0.f, C = 0.f;
        for (int i = 0; i < 8; i++) { S += rs[i]; C += rc[i]; }
        (tower ? g_S2p : g_S2v)[n] = S;
        (tower ? g_c2p : g_c2v)[n] = bi[n] + C;
    }
}

__global__ void prep3(const float* __restrict__ ln3_w, const float* __restrict__ ln3_b,
                      const float* __restrict__ n3g,  const float* __restrict__ n3b,
                      const float* __restrict__ p3w,  const float* __restrict__ p3b,
                      const float* __restrict__ pn3g, const float* __restrict__ pn3b)
{
    const int n = threadIdx.x;
    g_a3v[n] = ln3_w[n] * n3g[n];
    #pragma unroll
    for (int j = 0; j < 10; j++)
        g_A3p[n*10 + j] = p3w[j*NH + n] * pn3g[n];
    __syncthreads();
    if (n == 0) {
        float S = 0.f, C = 0.f;
        for (int k = 0; k < NH; k++) { S += g_a3v[k]; C += ln3_w[k] * n3b[k]; }
        g_S3v = S; g_c3v = ln3_b[0] + C;
    }
    if (n >= 1 && n <= 10) {
        int j = n - 1;
        float S = 0.f, C = 0.f;
        for (int k = 0; k < NH; k++) { S += g_A3p[k*10 + j]; C += p3w[j*NH + k] * pn3b[k]; }
        g_S3p[j] = S; g_c3p[j] = p3b[j] + C;
    }
}

// ===========================================================================
// Main kernel: 64 rows/CTA, warp tile 32x64, fp16 MMA, A2 stays in smem
// (tower-serial order: GEMM1v->GEMM2v->head_v->GEMM1p->GEMM2p->head_p)
// ===========================================================================
__global__ __launch_bounds__(NTHR, 2)
void bcq_mma(const float* __restrict__ cum, const float* __restrict__ feat,
             const float* __restrict__ pos, float* __restrict__ out, int N)
{
    extern __shared__ char smem[];
    const uint32_t sb = smem_u32(smem);
    const int t = threadIdx.x, wid = t >> 5, l = t & 31;
    const int mg = wid >> 2, ng = wid & 3;          // rows mg*32+, cols ng*64+
    const int ql = l >> 2, qc = l & 3;
    const long rowBase = (long)blockIdx.x * MROWS;

    float2* stat1  = (float2*)(smem + SM_STAT1);
    float2* stat2  = (float2*)(smem + SM_STAT2);
    float2* statC  = (float2*)(smem + SM_SCRATCH);
    unsigned short* A1_sm = (unsigned short*)(smem + SM_A1);
    char* A2_sm = smem + SM_A2;

    // ---- zero A1 region (layer1 k-pad 292..303 must be 0) ----
    {
        uint4 z; z.x = z.y = z.z = z.w = 0;
        uint4* a4 = (uint4*)smem;
        for (int i = t; i < 41984/16; i += NTHR) a4[i] = z;
    }
    __syncthreads();

    // ---- phase 1: x -> A1 fp16 smem + LN1 stats ----
    {
        const int row = t >> 2, q = t & 3;
        long gr = rowBase + row;
        long grl = gr < N ? gr : (long)N - 1;
        const float* c0 = cum  + grl * 146;
        const float* f0 = feat + grl * 136;
        const float* p0 = pos  + grl * 10;
        float s = 0.f, ss = 0.f;
        for (int k = q*73; k < q*73 + 73; k++) {
            float x = (k < 146) ? c0[k] : (k < 282 ? f0[k-146] : p0[k-282]);
            s += x; ss += x*x;
            A1_sm[row*LDA1 + k] = f2h(x);
        }
        s = qsum(s); ss = qsum(ss);
        if (q == 0) {
            const float inv = 1.f / (float)K1;
            float m = s * inv;
            float var = fmaxf(ss * inv - m*m, 0.f);
            stat1[row] = make_float2(m, rsqrtf(var + 1e-5f));
        }
    }
    __syncthreads();

    float c[2][8][4];

    // ---- GEMM: B from L2 in fragment order, double-buffered in regs ----
    auto gemm = [&](const uint4* __restrict__ Bimg, int KT, int lda, uint32_t aSm) {
        #pragma unroll
        for (int mt = 0; mt < 2; mt++)
            #pragma unroll
            for (int nt = 0; nt < 8; nt++)
                #pragma unroll
                for (int i = 0; i < 4; i++) c[mt][nt][i] = 0.f;

        const int arow = l & 15, akh = l >> 4;
        const uint4* Bp = Bimg + (size_t)(ng*4)*32 + l;

        uint4 bc[4], bn[4];
        #pragma unroll
        for (int j = 0; j < 4; j++) bc[j] = Bp[j*32];

        #pragma unroll 1
        for (int ch = 0; ch < KT; ch++) {
            if (ch + 1 < KT) {
                #pragma unroll
                for (int j = 0; j < 4; j++) bn[j] = Bp[((ch+1)*16 + j)*32];
            }
            uint32_t ah[2][4];
            #pragma unroll
            for (int mt = 0; mt < 2; mt++) {
                uint32_t ao = (uint32_t)(((mg*32 + mt*16 + arow)*lda + ch*16 + akh*8) * 2);
                ldsm_x4(aSm + ao, ah[mt]);
            }
            #pragma unroll
            for (int nt = 0; nt < 8; nt++) {
                uint32_t b0 = (nt & 1) ? bc[nt>>1].z : bc[nt>>1].x;
                uint32_t b1 = (nt & 1) ? bc[nt>>1].w : bc[nt>>1].y;
                mma_f16(c[0][nt], ah[0], b0, b1);
                mma_f16(c[1][nt], ah[1], b0, b1);
            }
            #pragma unroll
            for (int j = 0; j < 4; j++) bc[j] = bn[j];
        }
    };

    // ---- mid epilogue: D -> h(relu) -> A2 smem (fp16); LN2 stats -> stat2 ----
    auto epi_mid = [&](const float* Sg, const float* cvg) {
        float Sv[16], Cv[16];
        #pragma unroll
        for (int nt = 0; nt < 8; nt++) {
            int n = ng*64 + nt*8 + qc*2;
            Sv[nt*2]   = Sg[n];   Sv[nt*2+1] = Sg[n+1];
            Cv[nt*2]   = cvg[n];  Cv[nt*2+1] = cvg[n+1];
        }
        #pragma unroll
        for (int mt = 0; mt < 2; mt++) {
            const int rl = mg*32 + mt*16 + ql, rh = rl + 8;
            float2 stl = stat1[rl], sth = stat1[rh];
            float sl = 0.f, ssl = 0.f, sh = 0.f, ssh = 0.f;
            #pragma unroll
            for (int nt = 0; nt < 8; nt++) {
                int n = ng*64 + nt*8 + qc*2;
                float* d = c[mt][nt];
                float h00 = fmaxf(stl.y*(d[0] - stl.x*Sv[nt*2])   + Cv[nt*2],   0.f);
                float h01 = fmaxf(stl.y*(d[1] - stl.x*Sv[nt*2+1]) + Cv[nt*2+1], 0.f);
                float h10 = fmaxf(sth.y*(d[2] - sth.x*Sv[nt*2])   + Cv[nt*2],   0.f);
                float h11 = fmaxf(sth.y*(d[3] - sth.x*Sv[nt*2+1]) + Cv[nt*2+1], 0.f);
                sl += h00 + h01; ssl += h00*h00 + h01*h01;
                sh += h10 + h11; ssh += h10*h10 + h11*h11;
                *(uint32_t*)(A2_sm + rl*528 + n*2) = (uint32_t)f2h(h00) | ((uint32_t)f2h(h01) << 16);
                *(uint32_t*)(A2_sm + rh*528 + n*2) = (uint32_t)f2h(h10) | ((uint32_t)f2h(h11) << 16);
            }
            sl = qsum(sl); ssl = qsum(ssl); sh = qsum(sh); ssh = qsum(ssh);
            if (qc == 0) {
                statC[rl*4 + ng] = make_float2(sl, ssl);
                statC[rh*4 + ng] = make_float2(sh, ssh);
            }
        }
        __syncthreads();
        if (ng == 0 && qc == 0) {
            #pragma unroll
            for (int mt = 0; mt < 2; mt++) {
                #pragma unroll
                for (int hh = 0; hh < 2; hh++) {
                    int r = mg*32 + mt*16 + ql + hh*8;
                    float s = 0.f, ss = 0.f;
                    #pragma unroll
                    for (int g = 0; g < 4; g++) {
                        float2 v = statC[r*4 + g];
                        s += v.x; ss += v.y;
                    }
                    const float inv = 1.f / (float)NH;
                    float m = s * inv;
                    float var = fmaxf(ss * inv - m*m, 0.f);
                    stat2[r] = make_float2(m, rsqrtf(var + 1e-5f));
                }
            }
        }
        __syncthreads();
    };

    // ======== value tower ========
    gemm(g_B1v, KT1, LDA1, sb + SM_A1);
    epi_mid(g_S1v, g_c1v);
    gemm(g_B2v, KT2, LDA2, sb + SM_A2);
    {
        float Sv[16], Cv[16], A3[16];
        #pragma unroll
        for (int nt = 0; nt < 8; nt++) {
            int n = ng*64 + nt*8 + qc*2;
            Sv[nt*2] = g_S2v[n]; Sv[nt*2+1] = g_S2v[n+1];
            Cv[nt*2] = g_c2v[n]; Cv[nt*2+1] = g_c2v[n+1];
            A3[nt*2] = g_a3v[n]; A3[nt*2+1] = g_a3v[n+1];
        }
        float4* vstat = (float4*)(smem + SM_SCRATCH);
        #pragma unroll
        for (int mt = 0; mt < 2; mt++) {
            const int rl = mg*32 + mt*16 + ql, rh = rl + 8;
            float2 stl = stat2[rl], sth = stat2[rh];
            float sl = 0.f, ssl = 0.f, vdl = 0.f, sh = 0.f, ssh = 0.f, vdh = 0.f;
            #pragma unroll
            for (int nt = 0; nt < 8; nt++) {
                float* d = c[mt][nt];
                float h00 = fmaxf(stl.y*(d[0] - stl.x*Sv[nt*2])   + Cv[nt*2],   0.f);
                float h01 = fmaxf(stl.y*(d[1] - stl.x*Sv[nt*2+1]) + Cv[nt*2+1], 0.f);
                float h10 = fmaxf(sth.y*(d[2] - sth.x*Sv[nt*2])   + Cv[nt*2],   0.f);
                float h11 = fmaxf(sth.y*(d[3] - sth.x*Sv[nt*2+1]) + Cv[nt*2+1], 0.f);
                sl += h00 + h01; ssl += h00*h00 + h01*h01;
                sh += h10 + h11; ssh += h10*h10 + h11*h11;
                vdl = fmaf(A3[nt*2], h00, fmaf(A3[nt*2+1], h01, vdl));
                vdh = fmaf(A3[nt*2], h10, fmaf(A3[nt*2+1], h11, vdh));
            }
            sl = qsum(sl); ssl = qsum(ssl); vdl = qsum(vdl);
            sh = qsum(sh); ssh = qsum(ssh); vdh = qsum(vdh);
            if (qc == 0) {
                vstat[rl*4 + ng] = make_float4(sl, ssl, vdl, 0.f);
                vstat[rh*4 + ng] = make_float4(sh, ssh, vdh, 0.f);
            }
        }
        __syncthreads();
        if (ng == 0 && qc == 0) {
            #pragma unroll
            for (int mt = 0; mt < 2; mt++) {
                #pragma unroll
                for (int hh = 0; hh < 2; hh++) {
                    int r = mg*32 + mt*16 + ql + hh*8;
                    float s = 0.f, ss = 0.f, vd = 0.f;
                    #pragma unroll
                    for (int g = 0; g < 4; g++) {
                        float4 v = vstat[r*4 + g];
                        s += v.x; ss += v.y; vd += v.z;
                    }
                    long gr = rowBase + r;
                    if (gr < N) {
                        const float inv = 1.f / (float)NH;
                        float m3 = s * inv;
                        float var3 = fmaxf(ss * inv - m3*m3, 0.f);
                        float rs3 = rsqrtf(var3 + 1e-5f);
                        out[gr] = rs3*(vd - m3*g_S3v) + g_c3v;
                    }
                }
            }
        }
        __syncthreads();
    }

    // ======== prob tower ========
    gemm(g_B1p, KT1, LDA1, sb + SM_A1);
    epi_mid(g_S1p, g_c1p);
    gemm(g_B2p, KT2, LDA2, sb + SM_A2);
    {
        float Sv[16], Cv[16];
        #pragma unroll
        for (int nt = 0; nt < 8; nt++) {
            int n = ng*64 + nt*8 + qc*2;
            Sv[nt*2] = g_S2p[n]; Sv[nt*2+1] = g_S2p[n+1];
            Cv[nt*2] = g_c2p[n]; Cv[nt*2+1] = g_c2p[n+1];
        }
        float* pstat = (float*)(smem + SM_SCRATCH);   // [64][4][12]
        #pragma unroll
        for (int mt = 0; mt < 2; mt++) {
            const int rl = mg*32 + mt*16 + ql, rh = rl + 8;
            float2 stl = stat2[rl], sth = stat2[rh];
            float sl = 0.f, ssl = 0.f, sh = 0.f, ssh = 0.f;
            float Pl[10], Ph[10];
            #pragma unroll
            for (int q = 0; q < 10; q++) { Pl[q] = 0.f; Ph[q] = 0.f; }
            #pragma unroll
            for (int nt = 0; nt < 8; nt++) {
                int n = ng*64 + nt*8 + qc*2;
                float* d = c[mt][nt];
                float h00 = fmaxf(stl.y*(d[0] - stl.x*Sv[nt*2])   + Cv[nt*2],   0.f);
                float h01 = fmaxf(stl.y*(d[1] - stl.x*Sv[nt*2+1]) + Cv[nt*2+1], 0.f);
                float h10 = fmaxf(sth.y*(d[2] - sth.x*Sv[nt*2])   + Cv[nt*2],   0.f);
                float h11 = fmaxf(sth.y*(d[3] - sth.x*Sv[nt*2+1]) + Cv[nt*2+1], 0.f);
                sl += h00 + h01; ssl += h00*h00 + h01*h01;
                sh += h10 + h11; ssh += h10*h10 + h11*h11;
                const float* a0 = g_A3p + n*10;
                const float* a1 = a0 + 10;
                #pragma unroll
                for (int q = 0; q < 10; q++) {
                    Pl[q] = fmaf(h00, a0[q], fmaf(h01, a1[q], Pl[q]));
                    Ph[q] = fmaf(h10, a0[q], fmaf(h11, a1[q], Ph[q]));
                }
            }
            sl = qsum(sl); ssl = qsum(ssl); sh = qsum(sh); ssh = qsum(ssh);
            #pragma unroll
            for (int q = 0; q < 10; q++) { Pl[q] = qsum(Pl[q]); Ph[q] = qsum(Ph[q]); }
            if (qc == 0) {
                float* pl = pstat + (rl*4 + ng)*12;
                float* ph = pstat + (rh*4 + ng)*12;
                pl[0] = sl; pl[1] = ssl;
                ph[0] = sh; ph[1] = ssh;
                #pragma unroll
                for (int q = 0; q < 10; q++) { pl[2+q] = Pl[q]; ph[2+q] = Ph[q]; }
            }
        }
        __syncthreads();
        if (ng == 0 && qc == 0) {
            #pragma unroll
            for (int mt = 0; mt < 2; mt++) {
                #pragma unroll
                for (int hh = 0; hh < 2; hh++) {
                    int r = mg*32 + mt*16 + ql + hh*8;
                    float s = 0.f, ss = 0.f;
                    float P[10];
                    #pragma unroll
                    for (int q = 0; q < 10; q++) P[q] = 0.f;
                    #pragma unroll
                    for (int g = 0; g < 4; g++) {
                        const float* v = pstat + (r*4 + g)*12;
                        s += v[0]; ss += v[1];
                        #pragma unroll
                        for (int q = 0; q < 10; q++) P[q] += v[2+q];
                    }
                    long gr = rowBase + r;
                    if (gr < N) {
                        const float inv = 1.f / (float)NH;
                        float m3 = s * inv;
                        float var3 = fmaxf(ss * inv - m3*m3, 0.f);
                        float rs3 = rsqrtf(var3 + 1e-5f);
                        float sc[10];
                        float mx = -3.4e38f;
                        #pragma unroll
                        for (int q = 0; q < 10; q++) {
                            sc[q] = rs3*(P[q] - m3*g_S3p[q]) + g_c3p[q];
                            mx = fmaxf(mx, sc[q]);
                        }
                        float se = 0.f;
                        #pragma unroll
                        for (int q = 0; q < 10; q++) se += expf(sc[q] - mx);
                        float lse = mx + logf(se);
                        float* lp = out + N + gr * 10;
                        float* so = out + N + (long)N * 10 + gr * 10;
                        #pragma unroll
                        for (int q = 0; q < 10; q++) {
                            lp[q] = sc[q] - lse;
                            so[q] = sc[q];
                        }
                    }
                }
            }
        }
    }
}

// ===========================================================================
extern "C" void kernel_launch(void* const* d_in, const int* in_sizes, int n_in,
                              void* d_out, int out_size) {
    const float* cum  = (const float*)d_in[0];
    const float* feat = (const float*)d_in[1];
    const float* pos  = (const float*)d_in[2];
    const int N = in_sizes[0] / 146;

    cudaFuncSetAttribute(bcq_mma, cudaFuncAttributeMaxDynamicSharedMemorySize, SMEM_TOTAL);

    prep1<<<512, 320>>>(
        (const float*)d_in[3],  (const float*)d_in[4],    // ln1_w, ln1_b
        (const float*)d_in[9],  (const float*)d_in[10],   // norm1_g, norm1_b
        (const float*)d_in[15], (const float*)d_in[16],   // prob1_w, prob1_b
        (const float*)d_in[21], (const float*)d_in[22]);  // pnorm1_g, pnorm1_b
    prep2<<<512, 256>>>(
        (const float*)d_in[5],  (const float*)d_in[6],    // ln2_w, ln2_b
        (const float*)d_in[11], (const float*)d_in[12],   // norm2_g, norm2_b
        (const float*)d_in[17], (const float*)d_in[18],   // prob2_w, prob2_b
        (const float*)d_in[23], (const float*)d_in[24]);  // pnorm2_g, pnorm2_b
    prep3<<<1, 256>>>(
        (const float*)d_in[7],  (const float*)d_in[8],    // ln3_w, ln3_b
        (const float*)d_in[13], (const float*)d_in[14],   // norm3_g, norm3_b
        (const float*)d_in[19], (const float*)d_in[20],   // prob3_w, prob3_b
        (const float*)d_in[25], (const float*)d_in[26]);  // pnorm3_g, pnorm3_b

    const int grid = (N + MROWS - 1) / MROWS;
    bcq_mma<<<grid, NTHR, SMEM_TOTAL>>>(cum, feat, pos, (float*)d_out, N);
}